// round 12
// baseline (speedup 1.0000x reference)
#include <cuda_runtime.h>
#include <math.h>

#define BATCH 8
#define PTS   2048
#define NPTS  (BATCH*PTS)      // 16384
#define KNN   20
#define NEDGE (NPTS*KNN)       // 327680

typedef unsigned long long u64;

// ---------------- scratch ----------------
__device__ __align__(16) float g_x0[NPTS*6];
__device__ __align__(16) float g_h [NPTS*192];
__device__ __align__(16) float g_xsq[NPTS];
__device__ __align__(16) int   g_knn[NEDGE];
__device__ __align__(16) float g_PQ[NPTS*128];
__device__ __align__(16) unsigned g_enc[NPTS*64];   // zero-init; decode_xsq re-zeroes
__device__ __align__(16) float g_t1[NPTS*1024];
__device__ __align__(16) float g_t2[NPTS*256];
__device__ __align__(16) float g_t3[NPTS*128];

// ---------------- packed f32x2 helpers ----------------
__device__ __forceinline__ void ffma2(u64& acc, u64 a, u64 b) {
    asm("fma.rn.f32x2 %0, %1, %2, %0;" : "+l"(acc) : "l"(a), "l"(b));
}
__device__ __forceinline__ u64 pack2(float lo, float hi) {
    u64 r; asm("mov.b64 %0, {%1, %2};" : "=l"(r) : "f"(lo), "f"(hi)); return r;
}
__device__ __forceinline__ float2 unpack2(u64 v) {
    float2 f; asm("mov.b64 {%0, %1}, %2;" : "=f"(f.x), "=f"(f.y) : "l"(v)); return f;
}
__device__ __forceinline__ unsigned encf(float f) {
    unsigned u = __float_as_uint(f);
    return (u & 0x80000000u) ? ~u : (u | 0x80000000u);
}
__device__ __forceinline__ float decf(unsigned e) {
    return __uint_as_float((e & 0x80000000u) ? (e & 0x7FFFFFFFu) : ~e);
}

// warp-distributed sorted top-K insert; thr = register copy of lane-19 key.
__device__ __forceinline__ void warp_accept(u64& slot, u64& thr, u64 key, int lane) {
    unsigned am = __ballot_sync(0xffffffffu, key < thr);
    while (am) {
        int l = __ffs(am) - 1; am &= am - 1;
        u64 nk = __shfl_sync(0xffffffffu, key, l);
        bool ins = nk < thr;
        unsigned m = __ballot_sync(0xffffffffu, slot > nk);
        u64 up = __shfl_up_sync(0xffffffffu, slot, 1);
        if (ins) {
            int pos = __ffs(m) - 1;
            if (lane == pos) slot = nk;
            else if (lane > pos) slot = up;
            thr = __shfl_sync(0xffffffffu, slot, 19);
        }
    }
}

// ---------------- build x0 + squared norm (fused) ----------------
__global__ void x0xsq_kernel(const float* __restrict__ feats, const float* __restrict__ pos) {
    int p = blockIdx.x * 256 + threadIdx.x;
    if (p >= NPTS) return;
    float v[6];
    v[0] = feats[p*3+0]; v[1] = feats[p*3+1]; v[2] = feats[p*3+2];
    v[3] = pos[p*3+0];   v[4] = pos[p*3+1];   v[5] = pos[p*3+2];
    float s = 0.f;
    #pragma unroll
    for (int f = 0; f < 6; f++) { g_x0[p*6+f] = v[f]; s += v[f]*v[f]; }
    g_xsq[p] = s;
}

// ---------------- warp-kNN, D=6 ----------------
__global__ __launch_bounds__(256) void knn6_kernel() {
    const int T = 128;
    __shared__ float cf[T*7];
    __shared__ float cn[T];
    int tid  = threadIdx.x;
    int lane = tid & 31;
    int w    = tid >> 5;
    int b    = blockIdx.y;
    int p    = b*PTS + blockIdx.x*8 + w;

    float xi[6];
    #pragma unroll
    for (int f = 0; f < 6; f++) xi[f] = g_x0[p*6 + f];
    float xin = g_xsq[p];

    u64 slot = ~0ULL, thr = ~0ULL;

    for (int t0 = 0; t0 < PTS; t0 += T) {
        int q0 = b*PTS + t0;
        __syncthreads();
        #pragma unroll
        for (int u = tid; u < T*6; u += 256) {
            int c = u / 6, f = u % 6;
            cf[c*7 + f] = g_x0[(q0 + c)*6 + f];
        }
        if (tid < T) cn[tid] = g_xsq[q0 + tid];
        __syncthreads();
        #pragma unroll
        for (int r = 0; r < 4; r++) {
            int c = r*32 + lane;
            float dot = 0.f;
            #pragma unroll
            for (int f = 0; f < 6; f++) dot += xi[f]*cf[c*7 + f];
            float dist = xin + cn[c] - 2.f*dot;
            u64 key = ((u64)encf(dist) << 32) | (unsigned)(q0 + c);
            warp_accept(slot, thr, key, lane);
        }
    }
    if (lane < KNN) g_knn[(size_t)p*KNN + lane] = (int)(slot & 0xFFFFFFFFu);
}

// ---------------- warp-kNN, D=64: warp handles 2 points ----------------
__global__ __launch_bounds__(128) void knn64_kernel(const float* __restrict__ X,
                                                    int stride, int off,
                                                    int* __restrict__ out) {
    const int T = 128;
    __shared__ float cf[T*68];
    __shared__ float cn[T];
    int tid  = threadIdx.x;
    int lane = tid & 31;
    int w    = tid >> 5;
    int b    = blockIdx.y;
    int p0   = b*PTS + blockIdx.x*8 + w*2;
    int p1   = p0 + 1;

    u64 xa[32], xb[32];
    #pragma unroll
    for (int q = 0; q < 32; q++) {
        xa[q] = pack2(X[(size_t)p0*stride + off + 2*q], X[(size_t)p0*stride + off + 2*q + 1]);
        xb[q] = pack2(X[(size_t)p1*stride + off + 2*q], X[(size_t)p1*stride + off + 2*q + 1]);
    }
    float xina = g_xsq[p0], xinb = g_xsq[p1];

    u64 sl0 = ~0ULL, th0 = ~0ULL, sl1 = ~0ULL, th1 = ~0ULL;

    for (int t0 = 0; t0 < PTS; t0 += T) {
        int q0 = b*PTS + t0;
        __syncthreads();
        #pragma unroll
        for (int u = tid; u < T*16; u += 128) {
            int c = u >> 4, fv = u & 15;
            *(float4*)&cf[c*68 + fv*4] =
                *(const float4*)&X[(size_t)(q0 + c)*stride + off + fv*4];
        }
        if (tid < T) cn[tid] = g_xsq[q0 + tid];
        __syncthreads();
        #pragma unroll
        for (int r = 0; r < 4; r++) {
            int c = r*32 + lane;
            const ulonglong2* cp = (const ulonglong2*)&cf[c*68];
            u64 a0=0,a1=0,a2=0,a3=0, b0=0,b1=0,b2=0,b3=0;
            #pragma unroll
            for (int q = 0; q < 16; q += 2) {
                ulonglong2 v0 = cp[q];
                ulonglong2 v1 = cp[q+1];
                ffma2(a0, xa[2*q],   v0.x);  ffma2(b0, xb[2*q],   v0.x);
                ffma2(a1, xa[2*q+1], v0.y);  ffma2(b1, xb[2*q+1], v0.y);
                ffma2(a2, xa[2*q+2], v1.x);  ffma2(b2, xb[2*q+2], v1.x);
                ffma2(a3, xa[2*q+3], v1.y);  ffma2(b3, xb[2*q+3], v1.y);
            }
            float2 s0 = unpack2(a0), s1 = unpack2(a1);
            float2 s2 = unpack2(a2), s3 = unpack2(a3);
            float dota = ((s0.x+s0.y) + (s1.x+s1.y)) + ((s2.x+s2.y) + (s3.x+s3.y));
            s0 = unpack2(b0); s1 = unpack2(b1); s2 = unpack2(b2); s3 = unpack2(b3);
            float dotb = ((s0.x+s0.y) + (s1.x+s1.y)) + ((s2.x+s2.y) + (s3.x+s3.y));
            float da = xina + cn[c] - 2.f*dota;
            float db = xinb + cn[c] - 2.f*dotb;
            u64 ka = ((u64)encf(da) << 32) | (unsigned)(q0 + c);
            u64 kb = ((u64)encf(db) << 32) | (unsigned)(q0 + c);
            warp_accept(sl0, th0, ka, lane);
            warp_accept(sl1, th1, kb, lane);
        }
    }
    if (lane < KNN) {
        out[(size_t)p0*KNN + lane] = (int)(sl0 & 0xFFFFFFFFu);
        out[(size_t)p1*KNN + lane] = (int)(sl1 & 0xFFFFFFFFu);
    }
}

// ---------------- layer-1 P/Q (D=6) ----------------
__global__ void pq6_kernel(const float* __restrict__ w1a, const float* __restrict__ b1a) {
    int t = blockIdx.x * 256 + threadIdx.x;
    if (t >= NPTS*16) return;
    int p = t >> 4, c4 = (t & 15) * 4;
    float x[6];
    #pragma unroll
    for (int f = 0; f < 6; f++) x[f] = g_x0[p*6 + f];
    float4 P = *(const float4*)&b1a[c4];
    float4 Q = make_float4(0.f, 0.f, 0.f, 0.f);
    #pragma unroll
    for (int f = 0; f < 6; f++) {
        float4 wt = *(const float4*)&w1a[f*64 + c4];
        float4 wb = *(const float4*)&w1a[(6+f)*64 + c4];
        float4 wd = make_float4(wt.x - wb.x, wt.y - wb.y, wt.z - wb.z, wt.w - wb.w);
        P.x += x[f]*wd.x; P.y += x[f]*wd.y; P.z += x[f]*wd.z; P.w += x[f]*wd.w;
        Q.x += x[f]*wb.x; Q.y += x[f]*wb.y; Q.z += x[f]*wb.z; Q.w += x[f]*wb.w;
    }
    *(float4*)&g_PQ[p*128 + c4]      = P;
    *(float4*)&g_PQ[p*128 + 64 + c4] = Q;
}

// ---------------- fused decode + re-zero + xsq ----------------
__global__ void decode_xsq_kernel(const float* __restrict__ bias, int off) {
    int gt   = blockIdx.x * 256 + threadIdx.x;
    int p    = gt >> 5;
    int lane = threadIdx.x & 31;
    if (p >= NPTS) return;
    unsigned e0 = g_enc[p*64 + lane];
    unsigned e1 = g_enc[p*64 + 32 + lane];
    g_enc[p*64 + lane]      = 0u;
    g_enc[p*64 + 32 + lane] = 0u;
    float v0 = decf(e0) + bias[lane];
    float v1 = decf(e1) + bias[lane + 32];
    g_h[(size_t)p*192 + off + lane]      = v0;
    g_h[(size_t)p*192 + off + 32 + lane] = v1;
    float s = v0*v0 + v1*v1;
    #pragma unroll
    for (int d = 16; d; d >>= 1) s += __shfl_xor_sync(0xffffffffu, s, d);
    if (lane == 0) g_xsq[p] = s;
}

// ---------------- plain / PQ GEMM: 256x64 block, 128 threads, 16x8 microtile ----------------
// MODE 0: C = act(A @ W + b), W row-major [Kd,N]
// MODE 1: PQ mode. W = raw edge weight [2*64, 64]. Block n0=0 computes
//         A @ (Wtop-Wbot) + b (P part); block n0=64 computes A @ Wbot (Q part, no bias).
#define GBM2 256
#define GBN 64
#define GBK 16

template<int MODE>
__device__ __forceinline__ void load_wtile(const float* __restrict__ W, int N,
                                           int n0, int wn, int kr,
                                           float4& w0v, float4& w1v) {
    if (MODE == 0) {
        const float* Wr = W + (size_t)kr*N + n0 + wn;
        w0v = *(const float4*)Wr;
        w1v = *(const float4*)(Wr + 4);
    } else {
        if (n0 == 0) {
            const float* Wt = W + (size_t)kr*64 + wn;
            const float* Wb = W + (size_t)(64 + kr)*64 + wn;
            float4 t0 = *(const float4*)Wt, t1 = *(const float4*)(Wt + 4);
            float4 b0 = *(const float4*)Wb, b1 = *(const float4*)(Wb + 4);
            w0v = make_float4(t0.x-b0.x, t0.y-b0.y, t0.z-b0.z, t0.w-b0.w);
            w1v = make_float4(t1.x-b1.x, t1.y-b1.y, t1.z-b1.z, t1.w-b1.w);
        } else {
            const float* Wb = W + (size_t)(64 + kr)*64 + wn;
            w0v = *(const float4*)Wb;
            w1v = *(const float4*)(Wb + 4);
        }
    }
}

template<int MODE>
__global__ __launch_bounds__(128) void gemm_kernel(
        const float* __restrict__ A, int lda, int aoff,
        const float* __restrict__ W, const float* __restrict__ bias,
        float* __restrict__ C, int M, int N, int Kd, int do_relu) {
    __shared__ float As[GBK][GBM2+4];
    __shared__ float Ws[GBK][GBN];

    int t  = threadIdx.x;
    int m0 = blockIdx.x * GBM2;
    int n0 = blockIdx.y * GBN;
    int ty = t >> 3, tx = t & 7;
    int arow = t >> 2;
    int acol = (t & 3) * 4;
    int wk = t >> 3, wn = (t & 7) * 8;

    u64 acc[8][8];
    #pragma unroll
    for (int i = 0; i < 8; i++)
        #pragma unroll
        for (int j = 0; j < 8; j++) acc[i][j] = 0ULL;

    const float* A0 = A + aoff + (size_t)(m0 + arow)*lda + acol;

    float4 aR[8], w0v, w1v;
    #pragma unroll
    for (int i = 0; i < 8; i++)
        aR[i] = *(const float4*)(A0 + (size_t)(32*i)*lda);
    load_wtile<MODE>(W, N, n0, wn, wk, w0v, w1v);

    for (int kk = 0; kk < Kd; kk += GBK) {
        __syncthreads();
        #pragma unroll
        for (int i = 0; i < 8; i++) {
            As[acol+0][arow + 32*i] = aR[i].x;
            As[acol+1][arow + 32*i] = aR[i].y;
            As[acol+2][arow + 32*i] = aR[i].z;
            As[acol+3][arow + 32*i] = aR[i].w;
        }
        *(float4*)&Ws[wk][wn]     = w0v;
        *(float4*)&Ws[wk][wn + 4] = w1v;
        __syncthreads();
        if (kk + GBK < Kd) {
            #pragma unroll
            for (int i = 0; i < 8; i++)
                aR[i] = *(const float4*)(A0 + (kk + GBK) + (size_t)(32*i)*lda);
            load_wtile<MODE>(W, N, n0, wn, kk + GBK + wk, w0v, w1v);
        }
        #pragma unroll
        for (int k = 0; k < GBK; k++) {
            ulonglong2 aA = *(const ulonglong2*)&As[k][ty*16];
            ulonglong2 aB = *(const ulonglong2*)&As[k][ty*16 + 4];
            ulonglong2 aC = *(const ulonglong2*)&As[k][ty*16 + 8];
            ulonglong2 aD = *(const ulonglong2*)&As[k][ty*16 + 12];
            u64 am[8] = {aA.x, aA.y, aB.x, aB.y, aC.x, aC.y, aD.x, aD.y};
            float4 w0 = *(const float4*)&Ws[k][tx*8];
            float4 w1 = *(const float4*)&Ws[k][tx*8 + 4];
            u64 wp[8];
            wp[0] = pack2(w0.x, w0.x); wp[1] = pack2(w0.y, w0.y);
            wp[2] = pack2(w0.z, w0.z); wp[3] = pack2(w0.w, w0.w);
            wp[4] = pack2(w1.x, w1.x); wp[5] = pack2(w1.y, w1.y);
            wp[6] = pack2(w1.z, w1.z); wp[7] = pack2(w1.w, w1.w);
            #pragma unroll
            for (int i = 0; i < 8; i++)
                #pragma unroll
                for (int j = 0; j < 8; j++)
                    ffma2(acc[i][j], am[i], wp[j]);
        }
    }

    float bb[8];
    if (MODE == 1 && n0 != 0) {
        #pragma unroll
        for (int j = 0; j < 8; j++) bb[j] = 0.f;
    } else {
        float4 bz0 = *(const float4*)&bias[n0 + tx*8];
        float4 bz1 = *(const float4*)&bias[n0 + tx*8 + 4];
        bb[0]=bz0.x; bb[1]=bz0.y; bb[2]=bz0.z; bb[3]=bz0.w;
        bb[4]=bz1.x; bb[5]=bz1.y; bb[6]=bz1.z; bb[7]=bz1.w;
    }
    #pragma unroll
    for (int i = 0; i < 8; i++) {
        float lo[8], hi[8];
        #pragma unroll
        for (int j = 0; j < 8; j++) {
            float2 v = unpack2(acc[i][j]);
            lo[j] = v.x + bb[j]; hi[j] = v.y + bb[j];
            if (do_relu) { lo[j] = fmaxf(lo[j], 0.f); hi[j] = fmaxf(hi[j], 0.f); }
        }
        int m = m0 + ty*16 + 2*i;
        float* Cr0 = &C[(size_t)m*N + n0 + tx*8];
        float* Cr1 = Cr0 + N;
        *(float4*)Cr0       = make_float4(lo[0],lo[1],lo[2],lo[3]);
        *(float4*)(Cr0 + 4) = make_float4(lo[4],lo[5],lo[6],lo[7]);
        *(float4*)Cr1       = make_float4(hi[0],hi[1],hi[2],hi[3]);
        *(float4*)(Cr1 + 4) = make_float4(hi[4],hi[5],hi[6],hi[7]);
    }
}

// ---------------- fused edge kernel: 256 threads, 128x64 tile, 4x8 microtile ----------------
#define GBM 128

__global__ __launch_bounds__(256) void edge_kernel(const float* __restrict__ W2) {
    __shared__ float As[GBK][GBM+4];
    __shared__ float Ws[GBK][GBN];
    __shared__ int   jb[GBM];

    int t  = threadIdx.x;
    int m0 = blockIdx.x * GBM;
    int ty = t >> 3;          // 0..31 -> rows ty*4..+3
    int tx = t & 7;           // cols tx*8

    u64 acc[2][8];
    #pragma unroll
    for (int i = 0; i < 2; i++)
        #pragma unroll
        for (int j = 0; j < 8; j++) acc[i][j] = 0ULL;

    if (t < GBM) jb[t] = g_knn[m0 + t];
    int srow = t >> 2;          // 0..63; rows srow, srow+64
    int sc4  = (t & 3) * 4;
    int wk = t >> 4;            // 0..15
    int wn = (t & 15) * 4;
    __syncthreads();

    float4 p4[2], q4[2], wv;
    #pragma unroll
    for (int i = 0; i < 2; i++) {
        int row = srow + 64*i;
        int pb  = (m0 + row) / KNN;
        p4[i] = *(const float4*)&g_PQ[(size_t)pb*128 + sc4];
        q4[i] = *(const float4*)&g_PQ[(size_t)jb[row]*128 + 64 + sc4];
    }
    wv = *(const float4*)&W2[(size_t)wk*64 + wn];

    #pragma unroll
    for (int kk = 0; kk < 64; kk += GBK) {
        __syncthreads();
        #pragma unroll
        for (int i = 0; i < 2; i++) {
            int row = srow + 64*i;
            As[sc4+0][row] = fmaxf(p4[i].x + q4[i].x, 0.f);
            As[sc4+1][row] = fmaxf(p4[i].y + q4[i].y, 0.f);
            As[sc4+2][row] = fmaxf(p4[i].z + q4[i].z, 0.f);
            As[sc4+3][row] = fmaxf(p4[i].w + q4[i].w, 0.f);
        }
        *(float4*)&Ws[wk][wn] = wv;
        __syncthreads();
        if (kk + GBK < 64) {
            #pragma unroll
            for (int i = 0; i < 2; i++) {
                int row = srow + 64*i;
                int pb  = (m0 + row) / KNN;
                p4[i] = *(const float4*)&g_PQ[(size_t)pb*128 + kk + GBK + sc4];
                q4[i] = *(const float4*)&g_PQ[(size_t)jb[row]*128 + 64 + kk + GBK + sc4];
            }
            wv = *(const float4*)&W2[(size_t)(kk + GBK + wk)*64 + wn];
        }
        #pragma unroll
        for (int k = 0; k < GBK; k++) {
            ulonglong2 aA = *(const ulonglong2*)&As[k][ty*4];
            u64 am[2] = {aA.x, aA.y};
            float4 w0 = *(const float4*)&Ws[k][tx*8];
            float4 w1 = *(const float4*)&Ws[k][tx*8 + 4];
            u64 wp[8];
            wp[0] = pack2(w0.x, w0.x); wp[1] = pack2(w0.y, w0.y);
            wp[2] = pack2(w0.z, w0.z); wp[3] = pack2(w0.w, w0.w);
            wp[4] = pack2(w1.x, w1.x); wp[5] = pack2(w1.y, w1.y);
            wp[6] = pack2(w1.z, w1.z); wp[7] = pack2(w1.w, w1.w);
            #pragma unroll
            for (int i = 0; i < 2; i++)
                #pragma unroll
                for (int j = 0; j < 8; j++)
                    ffma2(acc[i][j], am[i], wp[j]);
        }
    }

    // per-point max epilogue over this thread's 4 consecutive edge rows
    int mb = m0 + ty*4;
    int curp = mb / KNN;
    float mx[8];
    #pragma unroll
    for (int j = 0; j < 8; j++) mx[j] = -3.4e38f;
    #pragma unroll
    for (int i = 0; i < 2; i++) {
        #pragma unroll
        for (int half = 0; half < 2; half++) {
            int rr = mb + 2*i + half;
            int pp = rr / KNN;
            if (pp != curp) {
                #pragma unroll
                for (int j = 0; j < 8; j++)
                    atomicMax(&g_enc[curp*64 + tx*8 + j], encf(mx[j]));
                curp = pp;
                #pragma unroll
                for (int j = 0; j < 8; j++) mx[j] = -3.4e38f;
            }
            #pragma unroll
            for (int j = 0; j < 8; j++) {
                float2 v = unpack2(acc[i][j]);
                float val = half ? v.y : v.x;
                mx[j] = fmaxf(mx[j], val);
            }
        }
    }
    #pragma unroll
    for (int j = 0; j < 8; j++)
        atomicMax(&g_enc[curp*64 + tx*8 + j], encf(mx[j]));
}

// ---------------- head final: 128->13 + log_softmax ----------------
__global__ void head4_kernel(const float* __restrict__ W,
                             const float* __restrict__ bias,
                             float* __restrict__ out) {
    int gt   = blockIdx.x * 256 + threadIdx.x;
    int warp = gt >> 5;
    int lane = threadIdx.x & 31;
    if (warp >= NPTS) return;
    float o = -3.4e38f;
    if (lane < 13) {
        float s = bias[lane];
        #pragma unroll 8
        for (int c = 0; c < 128; c++)
            s += g_t3[(size_t)warp*128 + c] * W[c*13 + lane];
        o = s;
    }
    float m = o;
    #pragma unroll
    for (int d = 16; d; d >>= 1) m = fmaxf(m, __shfl_xor_sync(0xffffffffu, m, d));
    float e = (lane < 13) ? expf(o - m) : 0.f;
    float ssum = e;
    #pragma unroll
    for (int d = 16; d; d >>= 1) ssum += __shfl_xor_sync(0xffffffffu, ssum, d);
    if (lane < 13) out[(size_t)warp*13 + lane] = o - m - logf(ssum);
}

// ---------------- host ----------------
static inline void run_gemm(const float* A, int lda, int aoff, const float* W,
                            const float* b, float* C, int M, int N, int Kd, int relu) {
    dim3 grid(M/GBM2, N/GBN);
    gemm_kernel<0><<<grid, 128>>>(A, lda, aoff, W, b, C, M, N, Kd, relu);
}
static inline void run_gemm_pq(const float* A, int aoff, const float* W,
                               const float* b, float* C) {
    dim3 grid(NPTS/GBM2, 2);
    gemm_kernel<1><<<grid, 128>>>(A, 192, aoff, W, b, C, NPTS, 128, 64, 0);
}

extern "C" void kernel_launch(void* const* d_in, const int* in_sizes, int n_in,
                              void* d_out, int out_size) {
    const float* feats = (const float*)d_in[0];
    const float* pos   = (const float*)d_in[1];
    const float* w1a = (const float*)d_in[3];
    const float* b1a = (const float*)d_in[4];
    const float* w1b = (const float*)d_in[5];
    const float* b1b = (const float*)d_in[6];
    const float* w2a = (const float*)d_in[7];
    const float* b2a = (const float*)d_in[8];
    const float* w2b = (const float*)d_in[9];
    const float* b2b = (const float*)d_in[10];
    const float* w3a = (const float*)d_in[11];
    const float* b3a = (const float*)d_in[12];
    const float* w3b = (const float*)d_in[13];
    const float* b3b = (const float*)d_in[14];
    const float* hw1 = (const float*)d_in[15];
    const float* hb1 = (const float*)d_in[16];
    const float* hw2 = (const float*)d_in[17];
    const float* hb2 = (const float*)d_in[18];
    const float* hw3 = (const float*)d_in[19];
    const float* hb3 = (const float*)d_in[20];
    const float* hw4 = (const float*)d_in[21];
    const float* hb4 = (const float*)d_in[22];
    float* out = (float*)d_out;

    float *h, *t1, *t2, *t3, *PQ;
    int *knn;
    cudaGetSymbolAddress((void**)&h,  g_h);
    cudaGetSymbolAddress((void**)&t1, g_t1);
    cudaGetSymbolAddress((void**)&t2, g_t2);
    cudaGetSymbolAddress((void**)&t3, g_t3);
    cudaGetSymbolAddress((void**)&PQ, g_PQ);
    cudaGetSymbolAddress((void**)&knn, g_knn);

    dim3 knn_grid(PTS/8, BATCH);
    int dg = NPTS*32/256;

    x0xsq_kernel<<<NPTS/256, 256>>>(feats, pos);                    // 1
    knn6_kernel<<<knn_grid, 256>>>();                               // 2
    pq6_kernel<<<NPTS*16/256, 256>>>(w1a, b1a);                     // 3
    // 4: knn64 PROBE (1/8 grid, reads valid g_PQ, writes scratch g_t2)
    knn64_kernel<<<dim3(PTS/8, 1), 128>>>(PQ, 128, 0, (int*)t2);    // 4 (profiled)

    // ---- layer 1 ----
    edge_kernel<<<NEDGE/GBM, 256>>>(w1b);                           // 5
    decode_xsq_kernel<<<dg, 256>>>(b1b, 0);                         // 6

    // ---- layer 2 ----
    knn64_kernel<<<knn_grid, 128>>>(h, 192, 0, knn);                // 7
    run_gemm_pq(h, 0,  w2a, b2a, PQ);                               // 8
    edge_kernel<<<NEDGE/GBM, 256>>>(w2b);                           // 9
    decode_xsq_kernel<<<dg, 256>>>(b2b, 64);                        // 10

    // ---- layer 3 ----
    knn64_kernel<<<knn_grid, 128>>>(h, 192, 64, knn);               // 11
    run_gemm_pq(h, 64, w3a, b3a, PQ);                               // 12
    edge_kernel<<<NEDGE/GBM, 256>>>(w3b);                           // 13
    decode_xsq_kernel<<<dg, 256>>>(b3b, 128);                       // 14

    // ---- head ----
    run_gemm(h,  192,  0, hw1, hb1, t1, NPTS, 1024, 192, 1);        // 15
    run_gemm(t1, 1024, 0, hw2, hb2, t2, NPTS, 256, 1024, 1);        // 16
    run_gemm(t2, 256,  0, hw3, hb3, t3, NPTS, 128, 256, 1);         // 17
    head4_kernel<<<NPTS*32/256, 256>>>(hw4, hb4, out);              // 18
}

// round 13
// speedup vs baseline: 1.1315x; 1.1315x over previous
#include <cuda_runtime.h>
#include <math.h>

#define BATCH 8
#define PTS   2048
#define NPTS  (BATCH*PTS)      // 16384
#define KNN   20
#define NEDGE (NPTS*KNN)       // 327680

typedef unsigned long long u64;

// ---------------- scratch ----------------
__device__ __align__(16) float g_x0[NPTS*6];
__device__ __align__(16) float g_h [NPTS*192];
__device__ __align__(16) float g_xsq[NPTS];
__device__ __align__(16) int   g_knn[NEDGE];
__device__ __align__(16) float g_PQ[NPTS*128];
__device__ __align__(16) unsigned g_enc[NPTS*64];   // zero-init; decode_xsq re-zeroes
__device__ __align__(16) float g_t1[NPTS*1024];
__device__ __align__(16) float g_t2[NPTS*256];
__device__ __align__(16) float g_t3[NPTS*128];

// ---------------- packed f32x2 helpers ----------------
__device__ __forceinline__ void ffma2(u64& acc, u64 a, u64 b) {
    asm("fma.rn.f32x2 %0, %1, %2, %0;" : "+l"(acc) : "l"(a), "l"(b));
}
__device__ __forceinline__ u64 pack2(float lo, float hi) {
    u64 r; asm("mov.b64 %0, {%1, %2};" : "=l"(r) : "f"(lo), "f"(hi)); return r;
}
__device__ __forceinline__ float2 unpack2(u64 v) {
    float2 f; asm("mov.b64 {%0, %1}, %2;" : "=f"(f.x), "=f"(f.y) : "l"(v)); return f;
}
__device__ __forceinline__ unsigned encf(float f) {
    unsigned u = __float_as_uint(f);
    return (u & 0x80000000u) ? ~u : (u | 0x80000000u);
}
__device__ __forceinline__ float decf(unsigned e) {
    return __uint_as_float((e & 0x80000000u) ? (e & 0x7FFFFFFFu) : ~e);
}

// warp-distributed sorted top-K insert; thr = register copy of lane-19 key.
__device__ __forceinline__ void warp_accept(u64& slot, u64& thr, u64 key, int lane) {
    unsigned am = __ballot_sync(0xffffffffu, key < thr);
    while (am) {
        int l = __ffs(am) - 1; am &= am - 1;
        u64 nk = __shfl_sync(0xffffffffu, key, l);
        bool ins = nk < thr;
        unsigned m = __ballot_sync(0xffffffffu, slot > nk);
        u64 up = __shfl_up_sync(0xffffffffu, slot, 1);
        if (ins) {
            int pos = __ffs(m) - 1;
            if (lane == pos) slot = nk;
            else if (lane > pos) slot = up;
            thr = __shfl_sync(0xffffffffu, slot, 19);
        }
    }
}

// ---------------- build x0 + squared norm (fused) ----------------
__global__ void x0xsq_kernel(const float* __restrict__ feats, const float* __restrict__ pos) {
    int p = blockIdx.x * 256 + threadIdx.x;
    if (p >= NPTS) return;
    float v[6];
    v[0] = feats[p*3+0]; v[1] = feats[p*3+1]; v[2] = feats[p*3+2];
    v[3] = pos[p*3+0];   v[4] = pos[p*3+1];   v[5] = pos[p*3+2];
    float s = 0.f;
    #pragma unroll
    for (int f = 0; f < 6; f++) { g_x0[p*6+f] = v[f]; s += v[f]*v[f]; }
    g_xsq[p] = s;
}

// ---------------- warp-kNN, D=6 ----------------
__global__ __launch_bounds__(256) void knn6_kernel() {
    const int T = 128;
    __shared__ float cf[T*7];
    __shared__ float cn[T];
    int tid  = threadIdx.x;
    int lane = tid & 31;
    int w    = tid >> 5;
    int b    = blockIdx.y;
    int p    = b*PTS + blockIdx.x*8 + w;

    float xi[6];
    #pragma unroll
    for (int f = 0; f < 6; f++) xi[f] = g_x0[p*6 + f];
    float xin = g_xsq[p];

    u64 slot = ~0ULL, thr = ~0ULL;

    for (int t0 = 0; t0 < PTS; t0 += T) {
        int q0 = b*PTS + t0;
        __syncthreads();
        #pragma unroll
        for (int u = tid; u < T*6; u += 256) {
            int c = u / 6, f = u % 6;
            cf[c*7 + f] = g_x0[(q0 + c)*6 + f];
        }
        if (tid < T) cn[tid] = g_xsq[q0 + tid];
        __syncthreads();
        #pragma unroll
        for (int r = 0; r < 4; r++) {
            int c = r*32 + lane;
            float dot = 0.f;
            #pragma unroll
            for (int f = 0; f < 6; f++) dot += xi[f]*cf[c*7 + f];
            float dist = xin + cn[c] - 2.f*dot;
            u64 key = ((u64)encf(dist) << 32) | (unsigned)(q0 + c);
            warp_accept(slot, thr, key, lane);
        }
    }
    if (lane < KNN) g_knn[(size_t)p*KNN + lane] = (int)(slot & 0xFFFFFFFFu);
}

// ---------------- warp-kNN, D=64: warp handles 2 points ----------------
__global__ __launch_bounds__(128) void knn64_kernel(const float* __restrict__ X,
                                                    int stride, int off) {
    const int T = 128;
    __shared__ float cf[T*68];
    __shared__ float cn[T];
    int tid  = threadIdx.x;
    int lane = tid & 31;
    int w    = tid >> 5;
    int b    = blockIdx.y;
    int p0   = b*PTS + blockIdx.x*8 + w*2;
    int p1   = p0 + 1;

    u64 xa[32], xb[32];
    #pragma unroll
    for (int q = 0; q < 32; q++) {
        xa[q] = pack2(X[(size_t)p0*stride + off + 2*q], X[(size_t)p0*stride + off + 2*q + 1]);
        xb[q] = pack2(X[(size_t)p1*stride + off + 2*q], X[(size_t)p1*stride + off + 2*q + 1]);
    }
    float xina = g_xsq[p0], xinb = g_xsq[p1];

    u64 sl0 = ~0ULL, th0 = ~0ULL, sl1 = ~0ULL, th1 = ~0ULL;

    for (int t0 = 0; t0 < PTS; t0 += T) {
        int q0 = b*PTS + t0;
        __syncthreads();
        #pragma unroll
        for (int u = tid; u < T*16; u += 128) {
            int c = u >> 4, fv = u & 15;
            *(float4*)&cf[c*68 + fv*4] =
                *(const float4*)&X[(size_t)(q0 + c)*stride + off + fv*4];
        }
        if (tid < T) cn[tid] = g_xsq[q0 + tid];
        __syncthreads();
        #pragma unroll
        for (int r = 0; r < 4; r++) {
            int c = r*32 + lane;
            const ulonglong2* cp = (const ulonglong2*)&cf[c*68];
            u64 a0=0,a1=0,a2=0,a3=0, b0=0,b1=0,b2=0,b3=0;
            #pragma unroll
            for (int q = 0; q < 16; q += 2) {
                ulonglong2 v0 = cp[q];
                ulonglong2 v1 = cp[q+1];
                ffma2(a0, xa[2*q],   v0.x);  ffma2(b0, xb[2*q],   v0.x);
                ffma2(a1, xa[2*q+1], v0.y);  ffma2(b1, xb[2*q+1], v0.y);
                ffma2(a2, xa[2*q+2], v1.x);  ffma2(b2, xb[2*q+2], v1.x);
                ffma2(a3, xa[2*q+3], v1.y);  ffma2(b3, xb[2*q+3], v1.y);
            }
            float2 s0 = unpack2(a0), s1 = unpack2(a1);
            float2 s2 = unpack2(a2), s3 = unpack2(a3);
            float dota = ((s0.x+s0.y) + (s1.x+s1.y)) + ((s2.x+s2.y) + (s3.x+s3.y));
            s0 = unpack2(b0); s1 = unpack2(b1); s2 = unpack2(b2); s3 = unpack2(b3);
            float dotb = ((s0.x+s0.y) + (s1.x+s1.y)) + ((s2.x+s2.y) + (s3.x+s3.y));
            float da = xina + cn[c] - 2.f*dota;
            float db = xinb + cn[c] - 2.f*dotb;
            u64 ka = ((u64)encf(da) << 32) | (unsigned)(q0 + c);
            u64 kb = ((u64)encf(db) << 32) | (unsigned)(q0 + c);
            warp_accept(sl0, th0, ka, lane);
            warp_accept(sl1, th1, kb, lane);
        }
    }
    if (lane < KNN) {
        g_knn[(size_t)p0*KNN + lane] = (int)(sl0 & 0xFFFFFFFFu);
        g_knn[(size_t)p1*KNN + lane] = (int)(sl1 & 0xFFFFFFFFu);
    }
}

// ---------------- layer-1 P/Q (D=6) ----------------
__global__ void pq6_kernel(const float* __restrict__ w1a, const float* __restrict__ b1a) {
    int t = blockIdx.x * 256 + threadIdx.x;
    if (t >= NPTS*16) return;
    int p = t >> 4, c4 = (t & 15) * 4;
    float x[6];
    #pragma unroll
    for (int f = 0; f < 6; f++) x[f] = g_x0[p*6 + f];
    float4 P = *(const float4*)&b1a[c4];
    float4 Q = make_float4(0.f, 0.f, 0.f, 0.f);
    #pragma unroll
    for (int f = 0; f < 6; f++) {
        float4 wt = *(const float4*)&w1a[f*64 + c4];
        float4 wb = *(const float4*)&w1a[(6+f)*64 + c4];
        float4 wd = make_float4(wt.x - wb.x, wt.y - wb.y, wt.z - wb.z, wt.w - wb.w);
        P.x += x[f]*wd.x; P.y += x[f]*wd.y; P.z += x[f]*wd.z; P.w += x[f]*wd.w;
        Q.x += x[f]*wb.x; Q.y += x[f]*wb.y; Q.z += x[f]*wb.z; Q.w += x[f]*wb.w;
    }
    *(float4*)&g_PQ[p*128 + c4]      = P;
    *(float4*)&g_PQ[p*128 + 64 + c4] = Q;
}

// ---------------- fused decode + re-zero + xsq ----------------
__global__ void decode_xsq_kernel(const float* __restrict__ bias, int off) {
    int gt   = blockIdx.x * 256 + threadIdx.x;
    int p    = gt >> 5;
    int lane = threadIdx.x & 31;
    if (p >= NPTS) return;
    unsigned e0 = g_enc[p*64 + lane];
    unsigned e1 = g_enc[p*64 + 32 + lane];
    g_enc[p*64 + lane]      = 0u;
    g_enc[p*64 + 32 + lane] = 0u;
    float v0 = decf(e0) + bias[lane];
    float v1 = decf(e1) + bias[lane + 32];
    g_h[(size_t)p*192 + off + lane]      = v0;
    g_h[(size_t)p*192 + off + 32 + lane] = v1;
    float s = v0*v0 + v1*v1;
    #pragma unroll
    for (int d = 16; d; d >>= 1) s += __shfl_xor_sync(0xffffffffu, s, d);
    if (lane == 0) g_xsq[p] = s;
}

// ---------------- plain / PQ GEMM: 256x64 block, 128 threads, 16x8 microtile ----------------
// MODE 0: C = act(A @ W + b), W row-major [Kd,N]
// MODE 1: PQ mode. W = raw edge weight [2*64, 64]. Block n0=0 computes
//         A @ (Wtop-Wbot) + b (P part); block n0=64 computes A @ Wbot (Q part, no bias).
#define GBM2 256
#define GBN 64
#define GBK 16

template<int MODE>
__device__ __forceinline__ void load_wtile(const float* __restrict__ W, int N,
                                           int n0, int wn, int kr,
                                           float4& w0v, float4& w1v) {
    if (MODE == 0) {
        const float* Wr = W + (size_t)kr*N + n0 + wn;
        w0v = *(const float4*)Wr;
        w1v = *(const float4*)(Wr + 4);
    } else {
        if (n0 == 0) {
            const float* Wt = W + (size_t)kr*64 + wn;
            const float* Wb = W + (size_t)(64 + kr)*64 + wn;
            float4 t0 = *(const float4*)Wt, t1 = *(const float4*)(Wt + 4);
            float4 b0 = *(const float4*)Wb, b1 = *(const float4*)(Wb + 4);
            w0v = make_float4(t0.x-b0.x, t0.y-b0.y, t0.z-b0.z, t0.w-b0.w);
            w1v = make_float4(t1.x-b1.x, t1.y-b1.y, t1.z-b1.z, t1.w-b1.w);
        } else {
            const float* Wb = W + (size_t)(64 + kr)*64 + wn;
            w0v = *(const float4*)Wb;
            w1v = *(const float4*)(Wb + 4);
        }
    }
}

template<int MODE>
__global__ __launch_bounds__(128) void gemm_kernel(
        const float* __restrict__ A, int lda, int aoff,
        const float* __restrict__ W, const float* __restrict__ bias,
        float* __restrict__ C, int M, int N, int Kd, int do_relu) {
    __shared__ float As[GBK][GBM2+4];
    __shared__ float Ws[GBK][GBN];

    int t  = threadIdx.x;
    int m0 = blockIdx.x * GBM2;
    int n0 = blockIdx.y * GBN;
    int ty = t >> 3, tx = t & 7;
    int arow = t >> 2;
    int acol = (t & 3) * 4;
    int wk = t >> 3, wn = (t & 7) * 8;

    u64 acc[8][8];
    #pragma unroll
    for (int i = 0; i < 8; i++)
        #pragma unroll
        for (int j = 0; j < 8; j++) acc[i][j] = 0ULL;

    const float* A0 = A + aoff + (size_t)(m0 + arow)*lda + acol;

    float4 aR[8], w0v, w1v;
    #pragma unroll
    for (int i = 0; i < 8; i++)
        aR[i] = *(const float4*)(A0 + (size_t)(32*i)*lda);
    load_wtile<MODE>(W, N, n0, wn, wk, w0v, w1v);

    for (int kk = 0; kk < Kd; kk += GBK) {
        __syncthreads();
        #pragma unroll
        for (int i = 0; i < 8; i++) {
            As[acol+0][arow + 32*i] = aR[i].x;
            As[acol+1][arow + 32*i] = aR[i].y;
            As[acol+2][arow + 32*i] = aR[i].z;
            As[acol+3][arow + 32*i] = aR[i].w;
        }
        *(float4*)&Ws[wk][wn]     = w0v;
        *(float4*)&Ws[wk][wn + 4] = w1v;
        __syncthreads();
        if (kk + GBK < Kd) {
            #pragma unroll
            for (int i = 0; i < 8; i++)
                aR[i] = *(const float4*)(A0 + (kk + GBK) + (size_t)(32*i)*lda);
            load_wtile<MODE>(W, N, n0, wn, kk + GBK + wk, w0v, w1v);
        }
        #pragma unroll
        for (int k = 0; k < GBK; k++) {
            ulonglong2 aA = *(const ulonglong2*)&As[k][ty*16];
            ulonglong2 aB = *(const ulonglong2*)&As[k][ty*16 + 4];
            ulonglong2 aC = *(const ulonglong2*)&As[k][ty*16 + 8];
            ulonglong2 aD = *(const ulonglong2*)&As[k][ty*16 + 12];
            u64 am[8] = {aA.x, aA.y, aB.x, aB.y, aC.x, aC.y, aD.x, aD.y};
            float4 w0 = *(const float4*)&Ws[k][tx*8];
            float4 w1 = *(const float4*)&Ws[k][tx*8 + 4];
            u64 wp[8];
            wp[0] = pack2(w0.x, w0.x); wp[1] = pack2(w0.y, w0.y);
            wp[2] = pack2(w0.z, w0.z); wp[3] = pack2(w0.w, w0.w);
            wp[4] = pack2(w1.x, w1.x); wp[5] = pack2(w1.y, w1.y);
            wp[6] = pack2(w1.z, w1.z); wp[7] = pack2(w1.w, w1.w);
            #pragma unroll
            for (int i = 0; i < 8; i++)
                #pragma unroll
                for (int j = 0; j < 8; j++)
                    ffma2(acc[i][j], am[i], wp[j]);
        }
    }

    float bb[8];
    if (MODE == 1 && n0 != 0) {
        #pragma unroll
        for (int j = 0; j < 8; j++) bb[j] = 0.f;
    } else {
        float4 bz0 = *(const float4*)&bias[n0 + tx*8];
        float4 bz1 = *(const float4*)&bias[n0 + tx*8 + 4];
        bb[0]=bz0.x; bb[1]=bz0.y; bb[2]=bz0.z; bb[3]=bz0.w;
        bb[4]=bz1.x; bb[5]=bz1.y; bb[6]=bz1.z; bb[7]=bz1.w;
    }
    #pragma unroll
    for (int i = 0; i < 8; i++) {
        float lo[8], hi[8];
        #pragma unroll
        for (int j = 0; j < 8; j++) {
            float2 v = unpack2(acc[i][j]);
            lo[j] = v.x + bb[j]; hi[j] = v.y + bb[j];
            if (do_relu) { lo[j] = fmaxf(lo[j], 0.f); hi[j] = fmaxf(hi[j], 0.f); }
        }
        int m = m0 + ty*16 + 2*i;
        float* Cr0 = &C[(size_t)m*N + n0 + tx*8];
        float* Cr1 = Cr0 + N;
        *(float4*)Cr0       = make_float4(lo[0],lo[1],lo[2],lo[3]);
        *(float4*)(Cr0 + 4) = make_float4(lo[4],lo[5],lo[6],lo[7]);
        *(float4*)Cr1       = make_float4(hi[0],hi[1],hi[2],hi[3]);
        *(float4*)(Cr1 + 4) = make_float4(hi[4],hi[5],hi[6],hi[7]);
    }
}

// ---------------- fused edge kernel: 128 threads, 8x8 microtile, coop gather ----------------
#define GBM 128

struct AccBlk { u64 a[4][8]; };

__device__ __forceinline__ void mt_compute(AccBlk& A_, const float As[GBK][GBM+4],
                                           const float Ws[GBK][GBN], int ty, int tx) {
    #pragma unroll
    for (int k = 0; k < GBK; k++) {
        ulonglong2 aA = *(const ulonglong2*)&As[k][ty*8];
        ulonglong2 aB = *(const ulonglong2*)&As[k][ty*8 + 4];
        u64 am[4] = {aA.x, aA.y, aB.x, aB.y};
        float4 w0 = *(const float4*)&Ws[k][tx*8];
        float4 w1 = *(const float4*)&Ws[k][tx*8 + 4];
        u64 wp[8];
        wp[0] = pack2(w0.x, w0.x); wp[1] = pack2(w0.y, w0.y);
        wp[2] = pack2(w0.z, w0.z); wp[3] = pack2(w0.w, w0.w);
        wp[4] = pack2(w1.x, w1.x); wp[5] = pack2(w1.y, w1.y);
        wp[6] = pack2(w1.z, w1.z); wp[7] = pack2(w1.w, w1.w);
        #pragma unroll
        for (int i = 0; i < 4; i++)
            #pragma unroll
            for (int j = 0; j < 8; j++)
                ffma2(A_.a[i][j], am[i], wp[j]);
    }
}

__global__ __launch_bounds__(128, 4) void edge_kernel(const float* __restrict__ W2) {
    __shared__ float As[GBK][GBM+4];
    __shared__ float Ws[GBK][GBN];
    __shared__ int   jb[GBM];

    int t  = threadIdx.x;
    int m0 = blockIdx.x * GBM;
    int ty = t >> 3, tx = t & 7;

    AccBlk acc;
    #pragma unroll
    for (int i = 0; i < 4; i++)
        #pragma unroll
        for (int j = 0; j < 8; j++) acc.a[i][j] = 0ULL;

    jb[t] = g_knn[m0 + t];
    int srow = t >> 2;              // staging rows: srow + 32*i
    int sc4  = (t & 3) * 4;         // k-chunk within tile: 4 floats
    int wk = t >> 3, wn = (t & 7) * 8;
    __syncthreads();

    // prefetch tile 0
    float4 p4[4], q4[4], w0v, w1v;
    #pragma unroll
    for (int i = 0; i < 4; i++) {
        int row = srow + 32*i;
        int pb  = (m0 + row) / KNN;
        p4[i] = *(const float4*)&g_PQ[(size_t)pb*128 + sc4];
        q4[i] = *(const float4*)&g_PQ[(size_t)jb[row]*128 + 64 + sc4];
    }
    {
        const float* Wr = &W2[(size_t)wk*64 + wn];
        w0v = *(const float4*)Wr;
        w1v = *(const float4*)(Wr + 4);
    }

    #pragma unroll
    for (int kk = 0; kk < 64; kk += GBK) {
        __syncthreads();
        #pragma unroll
        for (int i = 0; i < 4; i++) {
            int row = srow + 32*i;
            As[sc4+0][row] = fmaxf(p4[i].x + q4[i].x, 0.f);
            As[sc4+1][row] = fmaxf(p4[i].y + q4[i].y, 0.f);
            As[sc4+2][row] = fmaxf(p4[i].z + q4[i].z, 0.f);
            As[sc4+3][row] = fmaxf(p4[i].w + q4[i].w, 0.f);
        }
        *(float4*)&Ws[wk][wn]     = w0v;
        *(float4*)&Ws[wk][wn + 4] = w1v;
        __syncthreads();
        if (kk + GBK < 64) {
            #pragma unroll
            for (int i = 0; i < 4; i++) {
                int row = srow + 32*i;
                int pb  = (m0 + row) / KNN;
                p4[i] = *(const float4*)&g_PQ[(size_t)pb*128 + kk + GBK + sc4];
                q4[i] = *(const float4*)&g_PQ[(size_t)jb[row]*128 + 64 + kk + GBK + sc4];
            }
            const float* Wr = &W2[(size_t)(kk + GBK + wk)*64 + wn];
            w0v = *(const float4*)Wr;
            w1v = *(const float4*)(Wr + 4);
        }
        mt_compute(acc, As, Ws, ty, tx);
    }

    int mb = m0 + ty*8;
    int curp = mb / KNN;
    float mx[8];
    #pragma unroll
    for (int j = 0; j < 8; j++) mx[j] = -3.4e38f;
    #pragma unroll
    for (int i = 0; i < 4; i++) {
        #pragma unroll
        for (int half = 0; half < 2; half++) {
            int rr = mb + 2*i + half;
            int pp = rr / KNN;
            if (pp != curp) {
                #pragma unroll
                for (int j = 0; j < 8; j++)
                    atomicMax(&g_enc[curp*64 + tx*8 + j], encf(mx[j]));
                curp = pp;
                #pragma unroll
                for (int j = 0; j < 8; j++) mx[j] = -3.4e38f;
            }
            #pragma unroll
            for (int j = 0; j < 8; j++) {
                float2 v = unpack2(acc.a[i][j]);
                float val = half ? v.y : v.x;
                mx[j] = fmaxf(mx[j], val);
            }
        }
    }
    #pragma unroll
    for (int j = 0; j < 8; j++)
        atomicMax(&g_enc[curp*64 + tx*8 + j], encf(mx[j]));
}

// ---------------- head final: 128->13 + log_softmax ----------------
__global__ void head4_kernel(const float* __restrict__ W,
                             const float* __restrict__ bias,
                             float* __restrict__ out) {
    int gt   = blockIdx.x * 256 + threadIdx.x;
    int warp = gt >> 5;
    int lane = threadIdx.x & 31;
    if (warp >= NPTS) return;
    float o = -3.4e38f;
    if (lane < 13) {
        float s = bias[lane];
        #pragma unroll 8
        for (int c = 0; c < 128; c++)
            s += g_t3[(size_t)warp*128 + c] * W[c*13 + lane];
        o = s;
    }
    float m = o;
    #pragma unroll
    for (int d = 16; d; d >>= 1) m = fmaxf(m, __shfl_xor_sync(0xffffffffu, m, d));
    float e = (lane < 13) ? expf(o - m) : 0.f;
    float ssum = e;
    #pragma unroll
    for (int d = 16; d; d >>= 1) ssum += __shfl_xor_sync(0xffffffffu, ssum, d);
    if (lane < 13) out[(size_t)warp*13 + lane] = o - m - logf(ssum);
}

// ---------------- host ----------------
static inline void run_gemm(const float* A, int lda, int aoff, const float* W,
                            const float* b, float* C, int M, int N, int Kd, int relu) {
    dim3 grid(M/GBM2, N/GBN);
    gemm_kernel<0><<<grid, 128>>>(A, lda, aoff, W, b, C, M, N, Kd, relu);
}
static inline void run_gemm_pq(const float* A, int aoff, const float* W,
                               const float* b, float* C) {
    dim3 grid(NPTS/GBM2, 2);
    gemm_kernel<1><<<grid, 128>>>(A, 192, aoff, W, b, C, NPTS, 128, 64, 0);
}

extern "C" void kernel_launch(void* const* d_in, const int* in_sizes, int n_in,
                              void* d_out, int out_size) {
    const float* feats = (const float*)d_in[0];
    const float* pos   = (const float*)d_in[1];
    const float* w1a = (const float*)d_in[3];
    const float* b1a = (const float*)d_in[4];
    const float* w1b = (const float*)d_in[5];
    const float* b1b = (const float*)d_in[6];
    const float* w2a = (const float*)d_in[7];
    const float* b2a = (const float*)d_in[8];
    const float* w2b = (const float*)d_in[9];
    const float* b2b = (const float*)d_in[10];
    const float* w3a = (const float*)d_in[11];
    const float* b3a = (const float*)d_in[12];
    const float* w3b = (const float*)d_in[13];
    const float* b3b = (const float*)d_in[14];
    const float* hw1 = (const float*)d_in[15];
    const float* hb1 = (const float*)d_in[16];
    const float* hw2 = (const float*)d_in[17];
    const float* hb2 = (const float*)d_in[18];
    const float* hw3 = (const float*)d_in[19];
    const float* hb3 = (const float*)d_in[20];
    const float* hw4 = (const float*)d_in[21];
    const float* hb4 = (const float*)d_in[22];
    float* out = (float*)d_out;

    float *h, *t1, *t2, *t3, *PQ;
    cudaGetSymbolAddress((void**)&h,  g_h);
    cudaGetSymbolAddress((void**)&t1, g_t1);
    cudaGetSymbolAddress((void**)&t2, g_t2);
    cudaGetSymbolAddress((void**)&t3, g_t3);
    cudaGetSymbolAddress((void**)&PQ, g_PQ);

    dim3 knn_grid(PTS/8, BATCH);
    int dg = NPTS*32/256;

    x0xsq_kernel<<<NPTS/256, 256>>>(feats, pos);                    // 1
    knn6_kernel<<<knn_grid, 256>>>();                               // 2
    pq6_kernel<<<NPTS*16/256, 256>>>(w1a, b1a);                     // 3
    edge_kernel<<<NEDGE/GBM, 128>>>(w1b);                           // 4 (profiled)
    decode_xsq_kernel<<<dg, 256>>>(b1b, 0);                         // 5

    // ---- layer 2 ----
    knn64_kernel<<<knn_grid, 128>>>(h, 192, 0);                     // 6
    run_gemm_pq(h, 0,  w2a, b2a, PQ);                               // 7
    edge_kernel<<<NEDGE/GBM, 128>>>(w2b);                           // 8
    decode_xsq_kernel<<<dg, 256>>>(b2b, 64);                        // 9

    // ---- layer 3 ----
    knn64_kernel<<<knn_grid, 128>>>(h, 192, 64);                    // 10
    run_gemm_pq(h, 64, w3a, b3a, PQ);                               // 11
    edge_kernel<<<NEDGE/GBM, 128>>>(w3b);                           // 12
    decode_xsq_kernel<<<dg, 256>>>(b3b, 128);                       // 13

    // ---- head ----
    run_gemm(h,  192,  0, hw1, hb1, t1, NPTS, 1024, 192, 1);        // 14
    run_gemm(t1, 1024, 0, hw2, hb2, t2, NPTS, 256, 1024, 1);        // 15
    run_gemm(t2, 256,  0, hw3, hb3, t3, NPTS, 128, 256, 1);         // 16
    head4_kernel<<<NPTS*32/256, 256>>>(hw4, hb4, out);              // 17
}

// round 14
// speedup vs baseline: 1.1345x; 1.0026x over previous
#include <cuda_runtime.h>
#include <math.h>

#define BATCH 8
#define PTS   2048
#define NPTS  (BATCH*PTS)      // 16384
#define KNN   20
#define NEDGE (NPTS*KNN)       // 327680

typedef unsigned long long u64;

// ---------------- scratch ----------------
__device__ __align__(16) float g_x0[NPTS*6];
__device__ __align__(16) float g_h [NPTS*192];
__device__ __align__(16) float g_xsq[NPTS];
__device__ __align__(16) int   g_knn[NEDGE];
__device__ __align__(16) float g_PQ[NPTS*128];
__device__ __align__(16) unsigned g_enc[NPTS*64];   // zero-init; decode_xsq re-zeroes
__device__ __align__(16) float g_t1[NPTS*1024];
__device__ __align__(16) float g_t2[NPTS*256];
__device__ __align__(16) float g_t3[NPTS*128];

// ---------------- packed f32x2 helpers ----------------
__device__ __forceinline__ void ffma2(u64& acc, u64 a, u64 b) {
    asm("fma.rn.f32x2 %0, %1, %2, %0;" : "+l"(acc) : "l"(a), "l"(b));
}
__device__ __forceinline__ u64 pack2(float lo, float hi) {
    u64 r; asm("mov.b64 %0, {%1, %2};" : "=l"(r) : "f"(lo), "f"(hi)); return r;
}
__device__ __forceinline__ float2 unpack2(u64 v) {
    float2 f; asm("mov.b64 {%0, %1}, %2;" : "=f"(f.x), "=f"(f.y) : "l"(v)); return f;
}
__device__ __forceinline__ unsigned encf(float f) {
    unsigned u = __float_as_uint(f);
    return (u & 0x80000000u) ? ~u : (u | 0x80000000u);
}
__device__ __forceinline__ float decf(unsigned e) {
    return __uint_as_float((e & 0x80000000u) ? (e & 0x7FFFFFFFu) : ~e);
}

// warp-distributed sorted top-K insert; thr = register copy of lane-19 key.
__device__ __forceinline__ void warp_accept(u64& slot, u64& thr, u64 key, int lane) {
    unsigned am = __ballot_sync(0xffffffffu, key < thr);
    while (am) {
        int l = __ffs(am) - 1; am &= am - 1;
        u64 nk = __shfl_sync(0xffffffffu, key, l);
        bool ins = nk < thr;
        unsigned m = __ballot_sync(0xffffffffu, slot > nk);
        u64 up = __shfl_up_sync(0xffffffffu, slot, 1);
        if (ins) {
            int pos = __ffs(m) - 1;
            if (lane == pos) slot = nk;
            else if (lane > pos) slot = up;
            thr = __shfl_sync(0xffffffffu, slot, 19);
        }
    }
}

// ---------------- build x0 + squared norm (fused) ----------------
__global__ void x0xsq_kernel(const float* __restrict__ feats, const float* __restrict__ pos) {
    int p = blockIdx.x * 256 + threadIdx.x;
    if (p >= NPTS) return;
    float v[6];
    v[0] = feats[p*3+0]; v[1] = feats[p*3+1]; v[2] = feats[p*3+2];
    v[3] = pos[p*3+0];   v[4] = pos[p*3+1];   v[5] = pos[p*3+2];
    float s = 0.f;
    #pragma unroll
    for (int f = 0; f < 6; f++) { g_x0[p*6+f] = v[f]; s += v[f]*v[f]; }
    g_xsq[p] = s;
}

// ---------------- warp-kNN, D=6 (candidate tile = 256) ----------------
__global__ __launch_bounds__(256) void knn6_kernel() {
    const int T = 256;
    __shared__ float cf[T*7];
    __shared__ float cn[T];
    int tid  = threadIdx.x;
    int lane = tid & 31;
    int w    = tid >> 5;
    int b    = blockIdx.y;
    int p    = b*PTS + blockIdx.x*8 + w;

    float xi[6];
    #pragma unroll
    for (int f = 0; f < 6; f++) xi[f] = g_x0[p*6 + f];
    float xin = g_xsq[p];

    u64 slot = ~0ULL, thr = ~0ULL;

    for (int t0 = 0; t0 < PTS; t0 += T) {
        int q0 = b*PTS + t0;
        __syncthreads();
        #pragma unroll
        for (int u = tid; u < T*6; u += 256) {
            int c = u / 6, f = u % 6;
            cf[c*7 + f] = g_x0[(q0 + c)*6 + f];
        }
        cn[tid] = g_xsq[q0 + tid];
        __syncthreads();
        #pragma unroll
        for (int r = 0; r < T/32; r++) {
            int c = r*32 + lane;
            float dot = 0.f;
            #pragma unroll
            for (int f = 0; f < 6; f++) dot += xi[f]*cf[c*7 + f];
            float dist = xin + cn[c] - 2.f*dot;
            u64 key = ((u64)encf(dist) << 32) | (unsigned)(q0 + c);
            warp_accept(slot, thr, key, lane);
        }
    }
    if (lane < KNN) g_knn[(size_t)p*KNN + lane] = (int)(slot & 0xFFFFFFFFu);
}

// ---------------- warp-kNN, D=64: warp handles 2 points ----------------
__global__ __launch_bounds__(128) void knn64_kernel(const float* __restrict__ X,
                                                    int stride, int off) {
    const int T = 128;
    __shared__ float cf[T*68];
    __shared__ float cn[T];
    int tid  = threadIdx.x;
    int lane = tid & 31;
    int w    = tid >> 5;
    int b    = blockIdx.y;
    int p0   = b*PTS + blockIdx.x*8 + w*2;
    int p1   = p0 + 1;

    u64 xa[32], xb[32];
    #pragma unroll
    for (int q = 0; q < 32; q++) {
        xa[q] = pack2(X[(size_t)p0*stride + off + 2*q], X[(size_t)p0*stride + off + 2*q + 1]);
        xb[q] = pack2(X[(size_t)p1*stride + off + 2*q], X[(size_t)p1*stride + off + 2*q + 1]);
    }
    float xina = g_xsq[p0], xinb = g_xsq[p1];

    u64 sl0 = ~0ULL, th0 = ~0ULL, sl1 = ~0ULL, th1 = ~0ULL;

    for (int t0 = 0; t0 < PTS; t0 += T) {
        int q0 = b*PTS + t0;
        __syncthreads();
        #pragma unroll
        for (int u = tid; u < T*16; u += 128) {
            int c = u >> 4, fv = u & 15;
            *(float4*)&cf[c*68 + fv*4] =
                *(const float4*)&X[(size_t)(q0 + c)*stride + off + fv*4];
        }
        if (tid < T) cn[tid] = g_xsq[q0 + tid];
        __syncthreads();
        #pragma unroll
        for (int r = 0; r < 4; r++) {
            int c = r*32 + lane;
            const ulonglong2* cp = (const ulonglong2*)&cf[c*68];
            u64 a0=0,a1=0,a2=0,a3=0, b0=0,b1=0,b2=0,b3=0;
            #pragma unroll
            for (int q = 0; q < 16; q += 2) {
                ulonglong2 v0 = cp[q];
                ulonglong2 v1 = cp[q+1];
                ffma2(a0, xa[2*q],   v0.x);  ffma2(b0, xb[2*q],   v0.x);
                ffma2(a1, xa[2*q+1], v0.y);  ffma2(b1, xb[2*q+1], v0.y);
                ffma2(a2, xa[2*q+2], v1.x);  ffma2(b2, xb[2*q+2], v1.x);
                ffma2(a3, xa[2*q+3], v1.y);  ffma2(b3, xb[2*q+3], v1.y);
            }
            float2 s0 = unpack2(a0), s1 = unpack2(a1);
            float2 s2 = unpack2(a2), s3 = unpack2(a3);
            float dota = ((s0.x+s0.y) + (s1.x+s1.y)) + ((s2.x+s2.y) + (s3.x+s3.y));
            s0 = unpack2(b0); s1 = unpack2(b1); s2 = unpack2(b2); s3 = unpack2(b3);
            float dotb = ((s0.x+s0.y) + (s1.x+s1.y)) + ((s2.x+s2.y) + (s3.x+s3.y));
            float da = xina + cn[c] - 2.f*dota;
            float db = xinb + cn[c] - 2.f*dotb;
            u64 ka = ((u64)encf(da) << 32) | (unsigned)(q0 + c);
            u64 kb = ((u64)encf(db) << 32) | (unsigned)(q0 + c);
            warp_accept(sl0, th0, ka, lane);
            warp_accept(sl1, th1, kb, lane);
        }
    }
    if (lane < KNN) {
        g_knn[(size_t)p0*KNN + lane] = (int)(sl0 & 0xFFFFFFFFu);
        g_knn[(size_t)p1*KNN + lane] = (int)(sl1 & 0xFFFFFFFFu);
    }
}

// ---------------- layer-1 P/Q (D=6) ----------------
__global__ void pq6_kernel(const float* __restrict__ w1a, const float* __restrict__ b1a) {
    int t = blockIdx.x * 256 + threadIdx.x;
    if (t >= NPTS*16) return;
    int p = t >> 4, c4 = (t & 15) * 4;
    float x[6];
    #pragma unroll
    for (int f = 0; f < 6; f++) x[f] = g_x0[p*6 + f];
    float4 P = *(const float4*)&b1a[c4];
    float4 Q = make_float4(0.f, 0.f, 0.f, 0.f);
    #pragma unroll
    for (int f = 0; f < 6; f++) {
        float4 wt = *(const float4*)&w1a[f*64 + c4];
        float4 wb = *(const float4*)&w1a[(6+f)*64 + c4];
        float4 wd = make_float4(wt.x - wb.x, wt.y - wb.y, wt.z - wb.z, wt.w - wb.w);
        P.x += x[f]*wd.x; P.y += x[f]*wd.y; P.z += x[f]*wd.z; P.w += x[f]*wd.w;
        Q.x += x[f]*wb.x; Q.y += x[f]*wb.y; Q.z += x[f]*wb.z; Q.w += x[f]*wb.w;
    }
    *(float4*)&g_PQ[p*128 + c4]      = P;
    *(float4*)&g_PQ[p*128 + 64 + c4] = Q;
}

// ---------------- fused decode + re-zero + xsq ----------------
__global__ void decode_xsq_kernel(const float* __restrict__ bias, int off) {
    int gt   = blockIdx.x * 256 + threadIdx.x;
    int p    = gt >> 5;
    int lane = threadIdx.x & 31;
    if (p >= NPTS) return;
    unsigned e0 = g_enc[p*64 + lane];
    unsigned e1 = g_enc[p*64 + 32 + lane];
    g_enc[p*64 + lane]      = 0u;
    g_enc[p*64 + 32 + lane] = 0u;
    float v0 = decf(e0) + bias[lane];
    float v1 = decf(e1) + bias[lane + 32];
    g_h[(size_t)p*192 + off + lane]      = v0;
    g_h[(size_t)p*192 + off + 32 + lane] = v1;
    float s = v0*v0 + v1*v1;
    #pragma unroll
    for (int d = 16; d; d >>= 1) s += __shfl_xor_sync(0xffffffffu, s, d);
    if (lane == 0) g_xsq[p] = s;
}

// ---------------- plain / PQ GEMM: 256x64 block, 128 threads, 16x8 microtile ----------------
#define GBM2 256
#define GBN 64
#define GBK 16

template<int MODE>
__device__ __forceinline__ void load_wtile(const float* __restrict__ W, int N,
                                           int n0, int wn, int kr,
                                           float4& w0v, float4& w1v) {
    if (MODE == 0) {
        const float* Wr = W + (size_t)kr*N + n0 + wn;
        w0v = *(const float4*)Wr;
        w1v = *(const float4*)(Wr + 4);
    } else {
        if (n0 == 0) {
            const float* Wt = W + (size_t)kr*64 + wn;
            const float* Wb = W + (size_t)(64 + kr)*64 + wn;
            float4 t0 = *(const float4*)Wt, t1 = *(const float4*)(Wt + 4);
            float4 b0 = *(const float4*)Wb, b1 = *(const float4*)(Wb + 4);
            w0v = make_float4(t0.x-b0.x, t0.y-b0.y, t0.z-b0.z, t0.w-b0.w);
            w1v = make_float4(t1.x-b1.x, t1.y-b1.y, t1.z-b1.z, t1.w-b1.w);
        } else {
            const float* Wb = W + (size_t)(64 + kr)*64 + wn;
            w0v = *(const float4*)Wb;
            w1v = *(const float4*)(Wb + 4);
        }
    }
}

template<int MODE>
__global__ __launch_bounds__(128) void gemm_kernel(
        const float* __restrict__ A, int lda, int aoff,
        const float* __restrict__ W, const float* __restrict__ bias,
        float* __restrict__ C, int M, int N, int Kd, int do_relu) {
    __shared__ float As[GBK][GBM2+4];
    __shared__ float Ws[GBK][GBN];

    int t  = threadIdx.x;
    int m0 = blockIdx.x * GBM2;
    int n0 = blockIdx.y * GBN;
    int ty = t >> 3, tx = t & 7;
    int arow = t >> 2;
    int acol = (t & 3) * 4;
    int wk = t >> 3, wn = (t & 7) * 8;

    u64 acc[8][8];
    #pragma unroll
    for (int i = 0; i < 8; i++)
        #pragma unroll
        for (int j = 0; j < 8; j++) acc[i][j] = 0ULL;

    const float* A0 = A + aoff + (size_t)(m0 + arow)*lda + acol;

    float4 aR[8], w0v, w1v;
    #pragma unroll
    for (int i = 0; i < 8; i++)
        aR[i] = *(const float4*)(A0 + (size_t)(32*i)*lda);
    load_wtile<MODE>(W, N, n0, wn, wk, w0v, w1v);

    for (int kk = 0; kk < Kd; kk += GBK) {
        __syncthreads();
        #pragma unroll
        for (int i = 0; i < 8; i++) {
            As[acol+0][arow + 32*i] = aR[i].x;
            As[acol+1][arow + 32*i] = aR[i].y;
            As[acol+2][arow + 32*i] = aR[i].z;
            As[acol+3][arow + 32*i] = aR[i].w;
        }
        *(float4*)&Ws[wk][wn]     = w0v;
        *(float4*)&Ws[wk][wn + 4] = w1v;
        __syncthreads();
        if (kk + GBK < Kd) {
            #pragma unroll
            for (int i = 0; i < 8; i++)
                aR[i] = *(const float4*)(A0 + (kk + GBK) + (size_t)(32*i)*lda);
            load_wtile<MODE>(W, N, n0, wn, kk + GBK + wk, w0v, w1v);
        }
        #pragma unroll
        for (int k = 0; k < GBK; k++) {
            ulonglong2 aA = *(const ulonglong2*)&As[k][ty*16];
            ulonglong2 aB = *(const ulonglong2*)&As[k][ty*16 + 4];
            ulonglong2 aC = *(const ulonglong2*)&As[k][ty*16 + 8];
            ulonglong2 aD = *(const ulonglong2*)&As[k][ty*16 + 12];
            u64 am[8] = {aA.x, aA.y, aB.x, aB.y, aC.x, aC.y, aD.x, aD.y};
            float4 w0 = *(const float4*)&Ws[k][tx*8];
            float4 w1 = *(const float4*)&Ws[k][tx*8 + 4];
            u64 wp[8];
            wp[0] = pack2(w0.x, w0.x); wp[1] = pack2(w0.y, w0.y);
            wp[2] = pack2(w0.z, w0.z); wp[3] = pack2(w0.w, w0.w);
            wp[4] = pack2(w1.x, w1.x); wp[5] = pack2(w1.y, w1.y);
            wp[6] = pack2(w1.z, w1.z); wp[7] = pack2(w1.w, w1.w);
            #pragma unroll
            for (int i = 0; i < 8; i++)
                #pragma unroll
                for (int j = 0; j < 8; j++)
                    ffma2(acc[i][j], am[i], wp[j]);
        }
    }

    float bb[8];
    if (MODE == 1 && n0 != 0) {
        #pragma unroll
        for (int j = 0; j < 8; j++) bb[j] = 0.f;
    } else {
        float4 bz0 = *(const float4*)&bias[n0 + tx*8];
        float4 bz1 = *(const float4*)&bias[n0 + tx*8 + 4];
        bb[0]=bz0.x; bb[1]=bz0.y; bb[2]=bz0.z; bb[3]=bz0.w;
        bb[4]=bz1.x; bb[5]=bz1.y; bb[6]=bz1.z; bb[7]=bz1.w;
    }
    #pragma unroll
    for (int i = 0; i < 8; i++) {
        float lo[8], hi[8];
        #pragma unroll
        for (int j = 0; j < 8; j++) {
            float2 v = unpack2(acc[i][j]);
            lo[j] = v.x + bb[j]; hi[j] = v.y + bb[j];
            if (do_relu) { lo[j] = fmaxf(lo[j], 0.f); hi[j] = fmaxf(hi[j], 0.f); }
        }
        int m = m0 + ty*16 + 2*i;
        float* Cr0 = &C[(size_t)m*N + n0 + tx*8];
        float* Cr1 = Cr0 + N;
        *(float4*)Cr0       = make_float4(lo[0],lo[1],lo[2],lo[3]);
        *(float4*)(Cr0 + 4) = make_float4(lo[4],lo[5],lo[6],lo[7]);
        *(float4*)Cr1       = make_float4(hi[0],hi[1],hi[2],hi[3]);
        *(float4*)(Cr1 + 4) = make_float4(hi[4],hi[5],hi[6],hi[7]);
    }
}

// ---------------- fused edge kernel: double-buffered, 1 sync per k-tile ----------------
#define GBM 128

struct AccBlk { u64 a[4][8]; };

__device__ __forceinline__ void mt_compute(AccBlk& A_, const float As[GBK][GBM+4],
                                           const float Ws[GBK][GBN], int ty, int tx) {
    #pragma unroll
    for (int k = 0; k < GBK; k++) {
        ulonglong2 aA = *(const ulonglong2*)&As[k][ty*8];
        ulonglong2 aB = *(const ulonglong2*)&As[k][ty*8 + 4];
        u64 am[4] = {aA.x, aA.y, aB.x, aB.y};
        float4 w0 = *(const float4*)&Ws[k][tx*8];
        float4 w1 = *(const float4*)&Ws[k][tx*8 + 4];
        u64 wp[8];
        wp[0] = pack2(w0.x, w0.x); wp[1] = pack2(w0.y, w0.y);
        wp[2] = pack2(w0.z, w0.z); wp[3] = pack2(w0.w, w0.w);
        wp[4] = pack2(w1.x, w1.x); wp[5] = pack2(w1.y, w1.y);
        wp[6] = pack2(w1.z, w1.z); wp[7] = pack2(w1.w, w1.w);
        #pragma unroll
        for (int i = 0; i < 4; i++)
            #pragma unroll
            for (int j = 0; j < 8; j++)
                ffma2(A_.a[i][j], am[i], wp[j]);
    }
}

__global__ __launch_bounds__(128, 4) void edge_kernel(const float* __restrict__ W2) {
    __shared__ float As[2][GBK][GBM+4];
    __shared__ float Ws[2][GBK][GBN];
    __shared__ int   jb[GBM];

    int t  = threadIdx.x;
    int m0 = blockIdx.x * GBM;
    int ty = t >> 3, tx = t & 7;

    AccBlk acc;
    #pragma unroll
    for (int i = 0; i < 4; i++)
        #pragma unroll
        for (int j = 0; j < 8; j++) acc.a[i][j] = 0ULL;

    jb[t] = g_knn[m0 + t];
    int srow = t >> 2;
    int sc4  = (t & 3) * 4;
    int wk = t >> 3, wn = (t & 7) * 8;
    __syncthreads();

    // prefetch tile 0 into registers
    float4 p4[4], q4[4], w0v, w1v;
    #pragma unroll
    for (int i = 0; i < 4; i++) {
        int row = srow + 32*i;
        int pb  = (m0 + row) / KNN;
        p4[i] = *(const float4*)&g_PQ[(size_t)pb*128 + sc4];
        q4[i] = *(const float4*)&g_PQ[(size_t)jb[row]*128 + 64 + sc4];
    }
    {
        const float* Wr = &W2[(size_t)wk*64 + wn];
        w0v = *(const float4*)Wr;
        w1v = *(const float4*)(Wr + 4);
    }

    #pragma unroll
    for (int kt = 0; kt < 4; kt++) {
        int buf = kt & 1;
        // store prefetched tile into its buffer
        #pragma unroll
        for (int i = 0; i < 4; i++) {
            int row = srow + 32*i;
            As[buf][sc4+0][row] = fmaxf(p4[i].x + q4[i].x, 0.f);
            As[buf][sc4+1][row] = fmaxf(p4[i].y + q4[i].y, 0.f);
            As[buf][sc4+2][row] = fmaxf(p4[i].z + q4[i].z, 0.f);
            As[buf][sc4+3][row] = fmaxf(p4[i].w + q4[i].w, 0.f);
        }
        *(float4*)&Ws[buf][wk][wn]     = w0v;
        *(float4*)&Ws[buf][wk][wn + 4] = w1v;
        __syncthreads();
        // prefetch next tile during compute
        if (kt < 3) {
            int kn = (kt + 1) * GBK;
            #pragma unroll
            for (int i = 0; i < 4; i++) {
                int row = srow + 32*i;
                int pb  = (m0 + row) / KNN;
                p4[i] = *(const float4*)&g_PQ[(size_t)pb*128 + kn + sc4];
                q4[i] = *(const float4*)&g_PQ[(size_t)jb[row]*128 + 64 + kn + sc4];
            }
            const float* Wr = &W2[(size_t)(kn + wk)*64 + wn];
            w0v = *(const float4*)Wr;
            w1v = *(const float4*)(Wr + 4);
        }
        mt_compute(acc, As[buf], Ws[buf], ty, tx);
        // no second sync: next iteration writes the OTHER buffer; overwrite of this
        // buffer happens two tiles later, after the next sync, by which time every
        // warp has finished this compute.
    }

    int mb = m0 + ty*8;
    int curp = mb / KNN;
    float mx[8];
    #pragma unroll
    for (int j = 0; j < 8; j++) mx[j] = -3.4e38f;
    #pragma unroll
    for (int i = 0; i < 4; i++) {
        #pragma unroll
        for (int half = 0; half < 2; half++) {
            int rr = mb + 2*i + half;
            int pp = rr / KNN;
            if (pp != curp) {
                #pragma unroll
                for (int j = 0; j < 8; j++)
                    atomicMax(&g_enc[curp*64 + tx*8 + j], encf(mx[j]));
                curp = pp;
                #pragma unroll
                for (int j = 0; j < 8; j++) mx[j] = -3.4e38f;
            }
            #pragma unroll
            for (int j = 0; j < 8; j++) {
                float2 v = unpack2(acc.a[i][j]);
                float val = half ? v.y : v.x;
                mx[j] = fmaxf(mx[j], val);
            }
        }
    }
    #pragma unroll
    for (int j = 0; j < 8; j++)
        atomicMax(&g_enc[curp*64 + tx*8 + j], encf(mx[j]));
}

// ---------------- head final: 128->13 + log_softmax ----------------
__global__ void head4_kernel(const float* __restrict__ W,
                             const float* __restrict__ bias,
                             float* __restrict__ out) {
    int gt   = blockIdx.x * 256 + threadIdx.x;
    int warp = gt >> 5;
    int lane = threadIdx.x & 31;
    if (warp >= NPTS) return;
    float o = -3.4e38f;
    if (lane < 13) {
        float s = bias[lane];
        #pragma unroll 8
        for (int c = 0; c < 128; c++)
            s += g_t3[(size_t)warp*128 + c] * W[c*13 + lane];
        o = s;
    }
    float m = o;
    #pragma unroll
    for (int d = 16; d; d >>= 1) m = fmaxf(m, __shfl_xor_sync(0xffffffffu, m, d));
    float e = (lane < 13) ? expf(o - m) : 0.f;
    float ssum = e;
    #pragma unroll
    for (int d = 16; d; d >>= 1) ssum += __shfl_xor_sync(0xffffffffu, ssum, d);
    if (lane < 13) out[(size_t)warp*13 + lane] = o - m - logf(ssum);
}

// ---------------- host ----------------
static inline void run_gemm(const float* A, int lda, int aoff, const float* W,
                            const float* b, float* C, int M, int N, int Kd, int relu) {
    dim3 grid(M/GBM2, N/GBN);
    gemm_kernel<0><<<grid, 128>>>(A, lda, aoff, W, b, C, M, N, Kd, relu);
}
static inline void run_gemm_pq(const float* A, int aoff, const float* W,
                               const float* b, float* C) {
    dim3 grid(NPTS/GBM2, 2);
    gemm_kernel<1><<<grid, 128>>>(A, 192, aoff, W, b, C, NPTS, 128, 64, 0);
}

extern "C" void kernel_launch(void* const* d_in, const int* in_sizes, int n_in,
                              void* d_out, int out_size) {
    const float* feats = (const float*)d_in[0];
    const float* pos   = (const float*)d_in[1];
    const float* w1a = (const float*)d_in[3];
    const float* b1a = (const float*)d_in[4];
    const float* w1b = (const float*)d_in[5];
    const float* b1b = (const float*)d_in[6];
    const float* w2a = (const float*)d_in[7];
    const float* b2a = (const float*)d_in[8];
    const float* w2b = (const float*)d_in[9];
    const float* b2b = (const float*)d_in[10];
    const float* w3a = (const float*)d_in[11];
    const float* b3a = (const float*)d_in[12];
    const float* w3b = (const float*)d_in[13];
    const float* b3b = (const float*)d_in[14];
    const float* hw1 = (const float*)d_in[15];
    const float* hb1 = (const float*)d_in[16];
    const float* hw2 = (const float*)d_in[17];
    const float* hb2 = (const float*)d_in[18];
    const float* hw3 = (const float*)d_in[19];
    const float* hb3 = (const float*)d_in[20];
    const float* hw4 = (const float*)d_in[21];
    const float* hb4 = (const float*)d_in[22];
    float* out = (float*)d_out;

    float *h, *t1, *t2, *t3, *PQ;
    cudaGetSymbolAddress((void**)&h,  g_h);
    cudaGetSymbolAddress((void**)&t1, g_t1);
    cudaGetSymbolAddress((void**)&t2, g_t2);
    cudaGetSymbolAddress((void**)&t3, g_t3);
    cudaGetSymbolAddress((void**)&PQ, g_PQ);

    dim3 knn_grid(PTS/8, BATCH);
    int dg = NPTS*32/256;

    x0xsq_kernel<<<NPTS/256, 256>>>(feats, pos);                    // 1
    knn6_kernel<<<knn_grid, 256>>>();                               // 2
    pq6_kernel<<<NPTS*16/256, 256>>>(w1a, b1a);                     // 3
    edge_kernel<<<NEDGE/GBM, 128>>>(w1b);                           // 4 (profiled)
    decode_xsq_kernel<<<dg, 256>>>(b1b, 0);                         // 5

    // ---- layer 2 ----
    knn64_kernel<<<knn_grid, 128>>>(h, 192, 0);                     // 6
    run_gemm_pq(h, 0,  w2a, b2a, PQ);                               // 7
    edge_kernel<<<NEDGE/GBM, 128>>>(w2b);                           // 8
    decode_xsq_kernel<<<dg, 256>>>(b2b, 64);                        // 9

    // ---- layer 3 ----
    knn64_kernel<<<knn_grid, 128>>>(h, 192, 64);                    // 10
    run_gemm_pq(h, 64, w3a, b3a, PQ);                               // 11
    edge_kernel<<<NEDGE/GBM, 128>>>(w3b);                           // 12
    decode_xsq_kernel<<<dg, 256>>>(b3b, 128);                       // 13

    // ---- head ----
    run_gemm(h,  192,  0, hw1, hb1, t1, NPTS, 1024, 192, 1);        // 14
    run_gemm(t1, 1024, 0, hw2, hb2, t2, NPTS, 256, 1024, 1);        // 15
    run_gemm(t2, 256,  0, hw3, hb3, t3, NPTS, 128, 256, 1);         // 16
    head4_kernel<<<NPTS*32/256, 256>>>(hw4, hb4, out);              // 17
}

// round 15
// speedup vs baseline: 1.1710x; 1.0322x over previous
#include <cuda_runtime.h>
#include <math.h>

#define BATCH 8
#define PTS   2048
#define NPTS  (BATCH*PTS)      // 16384
#define KNN   20
#define NEDGE (NPTS*KNN)       // 327680

typedef unsigned long long u64;

// ---------------- scratch ----------------
__device__ __align__(16) float g_x0[NPTS*6];
__device__ __align__(16) float g_h [NPTS*192];
__device__ __align__(16) float g_xsq[NPTS];
__device__ __align__(16) int   g_knn[NEDGE];
__device__ __align__(16) float g_PQ[NPTS*128];
__device__ __align__(16) unsigned g_enc[NPTS*64];   // zero-init; decode_xsq re-zeroes
__device__ __align__(16) float g_t1[NPTS*1024];
__device__ __align__(16) float g_t2[NPTS*256];
__device__ __align__(16) float g_t3[NPTS*128];

// ---------------- packed f32x2 helpers ----------------
__device__ __forceinline__ void ffma2(u64& acc, u64 a, u64 b) {
    asm("fma.rn.f32x2 %0, %1, %2, %0;" : "+l"(acc) : "l"(a), "l"(b));
}
__device__ __forceinline__ u64 pack2(float lo, float hi) {
    u64 r; asm("mov.b64 %0, {%1, %2};" : "=l"(r) : "f"(lo), "f"(hi)); return r;
}
__device__ __forceinline__ float2 unpack2(u64 v) {
    float2 f; asm("mov.b64 {%0, %1}, %2;" : "=f"(f.x), "=f"(f.y) : "l"(v)); return f;
}
__device__ __forceinline__ unsigned encf(float f) {
    unsigned u = __float_as_uint(f);
    return (u & 0x80000000u) ? ~u : (u | 0x80000000u);
}
__device__ __forceinline__ float decf(unsigned e) {
    return __uint_as_float((e & 0x80000000u) ? (e & 0x7FFFFFFFu) : ~e);
}

// warp-distributed sorted top-K insert; thr = register copy of lane-19 key.
__device__ __forceinline__ void warp_accept(u64& slot, u64& thr, u64 key, int lane) {
    unsigned am = __ballot_sync(0xffffffffu, key < thr);
    while (am) {
        int l = __ffs(am) - 1; am &= am - 1;
        u64 nk = __shfl_sync(0xffffffffu, key, l);
        bool ins = nk < thr;
        unsigned m = __ballot_sync(0xffffffffu, slot > nk);
        u64 up = __shfl_up_sync(0xffffffffu, slot, 1);
        if (ins) {
            int pos = __ffs(m) - 1;
            if (lane == pos) slot = nk;
            else if (lane > pos) slot = up;
            thr = __shfl_sync(0xffffffffu, slot, 19);
        }
    }
}

// ---------------- build x0 + squared norm (fused) ----------------
__global__ void x0xsq_kernel(const float* __restrict__ feats, const float* __restrict__ pos) {
    int p = blockIdx.x * 256 + threadIdx.x;
    if (p >= NPTS) return;
    float v[6];
    v[0] = feats[p*3+0]; v[1] = feats[p*3+1]; v[2] = feats[p*3+2];
    v[3] = pos[p*3+0];   v[4] = pos[p*3+1];   v[5] = pos[p*3+2];
    float s = 0.f;
    #pragma unroll
    for (int f = 0; f < 6; f++) { g_x0[p*6+f] = v[f]; s += v[f]*v[f]; }
    g_xsq[p] = s;
}

// ---------------- warp-kNN, D=6 (candidate tile = 256) ----------------
__global__ __launch_bounds__(256) void knn6_kernel() {
    const int T = 256;
    __shared__ float cf[T*7];
    __shared__ float cn[T];
    int tid  = threadIdx.x;
    int lane = tid & 31;
    int w    = tid >> 5;
    int b    = blockIdx.y;
    int p    = b*PTS + blockIdx.x*8 + w;

    float xi[6];
    #pragma unroll
    for (int f = 0; f < 6; f++) xi[f] = g_x0[p*6 + f];
    float xin = g_xsq[p];

    u64 slot = ~0ULL, thr = ~0ULL;

    for (int t0 = 0; t0 < PTS; t0 += T) {
        int q0 = b*PTS + t0;
        __syncthreads();
        #pragma unroll
        for (int u = tid; u < T*6; u += 256) {
            int c = u / 6, f = u % 6;
            cf[c*7 + f] = g_x0[(q0 + c)*6 + f];
        }
        cn[tid] = g_xsq[q0 + tid];
        __syncthreads();
        #pragma unroll
        for (int r = 0; r < T/32; r++) {
            int c = r*32 + lane;
            float dot = 0.f;
            #pragma unroll
            for (int f = 0; f < 6; f++) dot += xi[f]*cf[c*7 + f];
            float dist = xin + cn[c] - 2.f*dot;
            u64 key = ((u64)encf(dist) << 32) | (unsigned)(q0 + c);
            warp_accept(slot, thr, key, lane);
        }
    }
    if (lane < KNN) g_knn[(size_t)p*KNN + lane] = (int)(slot & 0xFFFFFFFFu);
}

// ---------------- warp-kNN, D=64: warp handles 2 points, queries in SHARED ----------------
__global__ __launch_bounds__(128, 5) void knn64_kernel(const float* __restrict__ X,
                                                       int stride, int off) {
    const int T = 128;
    __shared__ float cf[T*68];
    __shared__ float cn[T];
    __shared__ float qs[8*64];       // 8 query rows for this block
    int tid  = threadIdx.x;
    int lane = tid & 31;
    int w    = tid >> 5;
    int b    = blockIdx.y;
    int pb   = b*PTS + blockIdx.x*8;
    int p0   = pb + w*2;
    int p1   = p0 + 1;

    // stage the block's 8 query rows into shared (coalesced, once)
    {
        int r  = tid >> 4;            // 0..7
        int c4 = (tid & 15) * 4;      // 0..60
        *(float4*)&qs[r*64 + c4] = *(const float4*)&X[(size_t)(pb + r)*stride + off + c4];
    }
    float xina = g_xsq[p0], xinb = g_xsq[p1];

    u64 sl0 = ~0ULL, th0 = ~0ULL, sl1 = ~0ULL, th1 = ~0ULL;
    const ulonglong2* qa = (const ulonglong2*)&qs[(w*2)*64];
    const ulonglong2* qb = (const ulonglong2*)&qs[(w*2+1)*64];

    for (int t0 = 0; t0 < PTS; t0 += T) {
        int q0 = b*PTS + t0;
        __syncthreads();
        #pragma unroll
        for (int u = tid; u < T*16; u += 128) {
            int c = u >> 4, fv = u & 15;
            *(float4*)&cf[c*68 + fv*4] =
                *(const float4*)&X[(size_t)(q0 + c)*stride + off + fv*4];
        }
        if (tid < T) cn[tid] = g_xsq[q0 + tid];
        __syncthreads();
        #pragma unroll
        for (int r = 0; r < 4; r++) {
            int c = r*32 + lane;
            const ulonglong2* cp = (const ulonglong2*)&cf[c*68];
            u64 a0=0,a1=0,a2=0,a3=0, b0=0,b1=0,b2=0,b3=0;
            #pragma unroll
            for (int q = 0; q < 16; q += 2) {
                ulonglong2 v0 = cp[q];
                ulonglong2 v1 = cp[q+1];
                ulonglong2 xav0 = qa[q];
                ulonglong2 xav1 = qa[q+1];
                ulonglong2 xbv0 = qb[q];
                ulonglong2 xbv1 = qb[q+1];
                ffma2(a0, xav0.x, v0.x);  ffma2(b0, xbv0.x, v0.x);
                ffma2(a1, xav0.y, v0.y);  ffma2(b1, xbv0.y, v0.y);
                ffma2(a2, xav1.x, v1.x);  ffma2(b2, xbv1.x, v1.x);
                ffma2(a3, xav1.y, v1.y);  ffma2(b3, xbv1.y, v1.y);
            }
            float2 s0 = unpack2(a0), s1 = unpack2(a1);
            float2 s2 = unpack2(a2), s3 = unpack2(a3);
            float dota = ((s0.x+s0.y) + (s1.x+s1.y)) + ((s2.x+s2.y) + (s3.x+s3.y));
            s0 = unpack2(b0); s1 = unpack2(b1); s2 = unpack2(b2); s3 = unpack2(b3);
            float dotb = ((s0.x+s0.y) + (s1.x+s1.y)) + ((s2.x+s2.y) + (s3.x+s3.y));
            float da = xina + cn[c] - 2.f*dota;
            float db = xinb + cn[c] - 2.f*dotb;
            u64 ka = ((u64)encf(da) << 32) | (unsigned)(q0 + c);
            u64 kb = ((u64)encf(db) << 32) | (unsigned)(q0 + c);
            warp_accept(sl0, th0, ka, lane);
            warp_accept(sl1, th1, kb, lane);
        }
    }
    if (lane < KNN) {
        g_knn[(size_t)p0*KNN + lane] = (int)(sl0 & 0xFFFFFFFFu);
        g_knn[(size_t)p1*KNN + lane] = (int)(sl1 & 0xFFFFFFFFu);
    }
}

// ---------------- layer-1 P/Q (D=6) ----------------
__global__ void pq6_kernel(const float* __restrict__ w1a, const float* __restrict__ b1a) {
    int t = blockIdx.x * 256 + threadIdx.x;
    if (t >= NPTS*16) return;
    int p = t >> 4, c4 = (t & 15) * 4;
    float x[6];
    #pragma unroll
    for (int f = 0; f < 6; f++) x[f] = g_x0[p*6 + f];
    float4 P = *(const float4*)&b1a[c4];
    float4 Q = make_float4(0.f, 0.f, 0.f, 0.f);
    #pragma unroll
    for (int f = 0; f < 6; f++) {
        float4 wt = *(const float4*)&w1a[f*64 + c4];
        float4 wb = *(const float4*)&w1a[(6+f)*64 + c4];
        float4 wd = make_float4(wt.x - wb.x, wt.y - wb.y, wt.z - wb.z, wt.w - wb.w);
        P.x += x[f]*wd.x; P.y += x[f]*wd.y; P.z += x[f]*wd.z; P.w += x[f]*wd.w;
        Q.x += x[f]*wb.x; Q.y += x[f]*wb.y; Q.z += x[f]*wb.z; Q.w += x[f]*wb.w;
    }
    *(float4*)&g_PQ[p*128 + c4]      = P;
    *(float4*)&g_PQ[p*128 + 64 + c4] = Q;
}

// ---------------- fused decode + re-zero + xsq ----------------
__global__ void decode_xsq_kernel(const float* __restrict__ bias, int off) {
    int gt   = blockIdx.x * 256 + threadIdx.x;
    int p    = gt >> 5;
    int lane = threadIdx.x & 31;
    if (p >= NPTS) return;
    unsigned e0 = g_enc[p*64 + lane];
    unsigned e1 = g_enc[p*64 + 32 + lane];
    g_enc[p*64 + lane]      = 0u;
    g_enc[p*64 + 32 + lane] = 0u;
    float v0 = decf(e0) + bias[lane];
    float v1 = decf(e1) + bias[lane + 32];
    g_h[(size_t)p*192 + off + lane]      = v0;
    g_h[(size_t)p*192 + off + 32 + lane] = v1;
    float s = v0*v0 + v1*v1;
    #pragma unroll
    for (int d = 16; d; d >>= 1) s += __shfl_xor_sync(0xffffffffu, s, d);
    if (lane == 0) g_xsq[p] = s;
}

// ---------------- plain / PQ GEMM: 256x64 block, 128 threads, 16x8 microtile ----------------
#define GBM2 256
#define GBN 64
#define GBK 16

template<int MODE>
__device__ __forceinline__ void load_wtile(const float* __restrict__ W, int N,
                                           int n0, int wn, int kr,
                                           float4& w0v, float4& w1v) {
    if (MODE == 0) {
        const float* Wr = W + (size_t)kr*N + n0 + wn;
        w0v = *(const float4*)Wr;
        w1v = *(const float4*)(Wr + 4);
    } else {
        if (n0 == 0) {
            const float* Wt = W + (size_t)kr*64 + wn;
            const float* Wb = W + (size_t)(64 + kr)*64 + wn;
            float4 t0 = *(const float4*)Wt, t1 = *(const float4*)(Wt + 4);
            float4 b0 = *(const float4*)Wb, b1 = *(const float4*)(Wb + 4);
            w0v = make_float4(t0.x-b0.x, t0.y-b0.y, t0.z-b0.z, t0.w-b0.w);
            w1v = make_float4(t1.x-b1.x, t1.y-b1.y, t1.z-b1.z, t1.w-b1.w);
        } else {
            const float* Wb = W + (size_t)(64 + kr)*64 + wn;
            w0v = *(const float4*)Wb;
            w1v = *(const float4*)(Wb + 4);
        }
    }
}

template<int MODE>
__global__ __launch_bounds__(128) void gemm_kernel(
        const float* __restrict__ A, int lda, int aoff,
        const float* __restrict__ W, const float* __restrict__ bias,
        float* __restrict__ C, int M, int N, int Kd, int do_relu) {
    __shared__ float As[GBK][GBM2+4];
    __shared__ float Ws[GBK][GBN];

    int t  = threadIdx.x;
    int m0 = blockIdx.x * GBM2;
    int n0 = blockIdx.y * GBN;
    int ty = t >> 3, tx = t & 7;
    int arow = t >> 2;
    int acol = (t & 3) * 4;
    int wk = t >> 3, wn = (t & 7) * 8;

    u64 acc[8][8];
    #pragma unroll
    for (int i = 0; i < 8; i++)
        #pragma unroll
        for (int j = 0; j < 8; j++) acc[i][j] = 0ULL;

    const float* A0 = A + aoff + (size_t)(m0 + arow)*lda + acol;

    float4 aR[8], w0v, w1v;
    #pragma unroll
    for (int i = 0; i < 8; i++)
        aR[i] = *(const float4*)(A0 + (size_t)(32*i)*lda);
    load_wtile<MODE>(W, N, n0, wn, wk, w0v, w1v);

    for (int kk = 0; kk < Kd; kk += GBK) {
        __syncthreads();
        #pragma unroll
        for (int i = 0; i < 8; i++) {
            As[acol+0][arow + 32*i] = aR[i].x;
            As[acol+1][arow + 32*i] = aR[i].y;
            As[acol+2][arow + 32*i] = aR[i].z;
            As[acol+3][arow + 32*i] = aR[i].w;
        }
        *(float4*)&Ws[wk][wn]     = w0v;
        *(float4*)&Ws[wk][wn + 4] = w1v;
        __syncthreads();
        if (kk + GBK < Kd) {
            #pragma unroll
            for (int i = 0; i < 8; i++)
                aR[i] = *(const float4*)(A0 + (kk + GBK) + (size_t)(32*i)*lda);
            load_wtile<MODE>(W, N, n0, wn, kk + GBK + wk, w0v, w1v);
        }
        #pragma unroll
        for (int k = 0; k < GBK; k++) {
            ulonglong2 aA = *(const ulonglong2*)&As[k][ty*16];
            ulonglong2 aB = *(const ulonglong2*)&As[k][ty*16 + 4];
            ulonglong2 aC = *(const ulonglong2*)&As[k][ty*16 + 8];
            ulonglong2 aD = *(const ulonglong2*)&As[k][ty*16 + 12];
            u64 am[8] = {aA.x, aA.y, aB.x, aB.y, aC.x, aC.y, aD.x, aD.y};
            float4 w0 = *(const float4*)&Ws[k][tx*8];
            float4 w1 = *(const float4*)&Ws[k][tx*8 + 4];
            u64 wp[8];
            wp[0] = pack2(w0.x, w0.x); wp[1] = pack2(w0.y, w0.y);
            wp[2] = pack2(w0.z, w0.z); wp[3] = pack2(w0.w, w0.w);
            wp[4] = pack2(w1.x, w1.x); wp[5] = pack2(w1.y, w1.y);
            wp[6] = pack2(w1.z, w1.z); wp[7] = pack2(w1.w, w1.w);
            #pragma unroll
            for (int i = 0; i < 8; i++)
                #pragma unroll
                for (int j = 0; j < 8; j++)
                    ffma2(acc[i][j], am[i], wp[j]);
        }
    }

    float bb[8];
    if (MODE == 1 && n0 != 0) {
        #pragma unroll
        for (int j = 0; j < 8; j++) bb[j] = 0.f;
    } else {
        float4 bz0 = *(const float4*)&bias[n0 + tx*8];
        float4 bz1 = *(const float4*)&bias[n0 + tx*8 + 4];
        bb[0]=bz0.x; bb[1]=bz0.y; bb[2]=bz0.z; bb[3]=bz0.w;
        bb[4]=bz1.x; bb[5]=bz1.y; bb[6]=bz1.z; bb[7]=bz1.w;
    }
    #pragma unroll
    for (int i = 0; i < 8; i++) {
        float lo[8], hi[8];
        #pragma unroll
        for (int j = 0; j < 8; j++) {
            float2 v = unpack2(acc[i][j]);
            lo[j] = v.x + bb[j]; hi[j] = v.y + bb[j];
            if (do_relu) { lo[j] = fmaxf(lo[j], 0.f); hi[j] = fmaxf(hi[j], 0.f); }
        }
        int m = m0 + ty*16 + 2*i;
        float* Cr0 = &C[(size_t)m*N + n0 + tx*8];
        float* Cr1 = Cr0 + N;
        *(float4*)Cr0       = make_float4(lo[0],lo[1],lo[2],lo[3]);
        *(float4*)(Cr0 + 4) = make_float4(lo[4],lo[5],lo[6],lo[7]);
        *(float4*)Cr1       = make_float4(hi[0],hi[1],hi[2],hi[3]);
        *(float4*)(Cr1 + 4) = make_float4(hi[4],hi[5],hi[6],hi[7]);
    }
}

// ---------------- fused edge kernel: double-buffered, 1 sync per k-tile ----------------
#define GBM 128

struct AccBlk { u64 a[4][8]; };

__device__ __forceinline__ void mt_compute(AccBlk& A_, const float As[GBK][GBM+4],
                                           const float Ws[GBK][GBN], int ty, int tx) {
    #pragma unroll
    for (int k = 0; k < GBK; k++) {
        ulonglong2 aA = *(const ulonglong2*)&As[k][ty*8];
        ulonglong2 aB = *(const ulonglong2*)&As[k][ty*8 + 4];
        u64 am[4] = {aA.x, aA.y, aB.x, aB.y};
        float4 w0 = *(const float4*)&Ws[k][tx*8];
        float4 w1 = *(const float4*)&Ws[k][tx*8 + 4];
        u64 wp[8];
        wp[0] = pack2(w0.x, w0.x); wp[1] = pack2(w0.y, w0.y);
        wp[2] = pack2(w0.z, w0.z); wp[3] = pack2(w0.w, w0.w);
        wp[4] = pack2(w1.x, w1.x); wp[5] = pack2(w1.y, w1.y);
        wp[6] = pack2(w1.z, w1.z); wp[7] = pack2(w1.w, w1.w);
        #pragma unroll
        for (int i = 0; i < 4; i++)
            #pragma unroll
            for (int j = 0; j < 8; j++)
                ffma2(A_.a[i][j], am[i], wp[j]);
    }
}

__global__ __launch_bounds__(128, 4) void edge_kernel(const float* __restrict__ W2) {
    __shared__ float As[2][GBK][GBM+4];
    __shared__ float Ws[2][GBK][GBN];
    __shared__ int   jb[GBM];

    int t  = threadIdx.x;
    int m0 = blockIdx.x * GBM;
    int ty = t >> 3, tx = t & 7;

    AccBlk acc;
    #pragma unroll
    for (int i = 0; i < 4; i++)
        #pragma unroll
        for (int j = 0; j < 8; j++) acc.a[i][j] = 0ULL;

    jb[t] = g_knn[m0 + t];
    int srow = t >> 2;
    int sc4  = (t & 3) * 4;
    int wk = t >> 3, wn = (t & 7) * 8;
    __syncthreads();

    float4 p4[4], q4[4], w0v, w1v;
    #pragma unroll
    for (int i = 0; i < 4; i++) {
        int row = srow + 32*i;
        int pb  = (m0 + row) / KNN;
        p4[i] = *(const float4*)&g_PQ[(size_t)pb*128 + sc4];
        q4[i] = *(const float4*)&g_PQ[(size_t)jb[row]*128 + 64 + sc4];
    }
    {
        const float* Wr = &W2[(size_t)wk*64 + wn];
        w0v = *(const float4*)Wr;
        w1v = *(const float4*)(Wr + 4);
    }

    #pragma unroll
    for (int kt = 0; kt < 4; kt++) {
        int buf = kt & 1;
        #pragma unroll
        for (int i = 0; i < 4; i++) {
            int row = srow + 32*i;
            As[buf][sc4+0][row] = fmaxf(p4[i].x + q4[i].x, 0.f);
            As[buf][sc4+1][row] = fmaxf(p4[i].y + q4[i].y, 0.f);
            As[buf][sc4+2][row] = fmaxf(p4[i].z + q4[i].z, 0.f);
            As[buf][sc4+3][row] = fmaxf(p4[i].w + q4[i].w, 0.f);
        }
        *(float4*)&Ws[buf][wk][wn]     = w0v;
        *(float4*)&Ws[buf][wk][wn + 4] = w1v;
        __syncthreads();
        if (kt < 3) {
            int kn = (kt + 1) * GBK;
            #pragma unroll
            for (int i = 0; i < 4; i++) {
                int row = srow + 32*i;
                int pb  = (m0 + row) / KNN;
                p4[i] = *(const float4*)&g_PQ[(size_t)pb*128 + kn + sc4];
                q4[i] = *(const float4*)&g_PQ[(size_t)jb[row]*128 + 64 + kn + sc4];
            }
            const float* Wr = &W2[(size_t)(kn + wk)*64 + wn];
            w0v = *(const float4*)Wr;
            w1v = *(const float4*)(Wr + 4);
        }
        mt_compute(acc, As[buf], Ws[buf], ty, tx);
    }

    int mb = m0 + ty*8;
    int curp = mb / KNN;
    float mx[8];
    #pragma unroll
    for (int j = 0; j < 8; j++) mx[j] = -3.4e38f;
    #pragma unroll
    for (int i = 0; i < 4; i++) {
        #pragma unroll
        for (int half = 0; half < 2; half++) {
            int rr = mb + 2*i + half;
            int pp = rr / KNN;
            if (pp != curp) {
                #pragma unroll
                for (int j = 0; j < 8; j++)
                    atomicMax(&g_enc[curp*64 + tx*8 + j], encf(mx[j]));
                curp = pp;
                #pragma unroll
                for (int j = 0; j < 8; j++) mx[j] = -3.4e38f;
            }
            #pragma unroll
            for (int j = 0; j < 8; j++) {
                float2 v = unpack2(acc.a[i][j]);
                float val = half ? v.y : v.x;
                mx[j] = fmaxf(mx[j], val);
            }
        }
    }
    #pragma unroll
    for (int j = 0; j < 8; j++)
        atomicMax(&g_enc[curp*64 + tx*8 + j], encf(mx[j]));
}

// ---------------- head final: 128->13 + log_softmax ----------------
__global__ void head4_kernel(const float* __restrict__ W,
                             const float* __restrict__ bias,
                             float* __restrict__ out) {
    int gt   = blockIdx.x * 256 + threadIdx.x;
    int warp = gt >> 5;
    int lane = threadIdx.x & 31;
    if (warp >= NPTS) return;
    float o = -3.4e38f;
    if (lane < 13) {
        float s = bias[lane];
        #pragma unroll 8
        for (int c = 0; c < 128; c++)
            s += g_t3[(size_t)warp*128 + c] * W[c*13 + lane];
        o = s;
    }
    float m = o;
    #pragma unroll
    for (int d = 16; d; d >>= 1) m = fmaxf(m, __shfl_xor_sync(0xffffffffu, m, d));
    float e = (lane < 13) ? expf(o - m) : 0.f;
    float ssum = e;
    #pragma unroll
    for (int d = 16; d; d >>= 1) ssum += __shfl_xor_sync(0xffffffffu, ssum, d);
    if (lane < 13) out[(size_t)warp*13 + lane] = o - m - logf(ssum);
}

// ---------------- host ----------------
static inline void run_gemm(const float* A, int lda, int aoff, const float* W,
                            const float* b, float* C, int M, int N, int Kd, int relu) {
    dim3 grid(M/GBM2, N/GBN);
    gemm_kernel<0><<<grid, 128>>>(A, lda, aoff, W, b, C, M, N, Kd, relu);
}
static inline void run_gemm_pq(const float* A, int aoff, const float* W,
                               const float* b, float* C) {
    dim3 grid(NPTS/GBM2, 2);
    gemm_kernel<1><<<grid, 128>>>(A, 192, aoff, W, b, C, NPTS, 128, 64, 0);
}

extern "C" void kernel_launch(void* const* d_in, const int* in_sizes, int n_in,
                              void* d_out, int out_size) {
    const float* feats = (const float*)d_in[0];
    const float* pos   = (const float*)d_in[1];
    const float* w1a = (const float*)d_in[3];
    const float* b1a = (const float*)d_in[4];
    const float* w1b = (const float*)d_in[5];
    const float* b1b = (const float*)d_in[6];
    const float* w2a = (const float*)d_in[7];
    const float* b2a = (const float*)d_in[8];
    const float* w2b = (const float*)d_in[9];
    const float* b2b = (const float*)d_in[10];
    const float* w3a = (const float*)d_in[11];
    const float* b3a = (const float*)d_in[12];
    const float* w3b = (const float*)d_in[13];
    const float* b3b = (const float*)d_in[14];
    const float* hw1 = (const float*)d_in[15];
    const float* hb1 = (const float*)d_in[16];
    const float* hw2 = (const float*)d_in[17];
    const float* hb2 = (const float*)d_in[18];
    const float* hw3 = (const float*)d_in[19];
    const float* hb3 = (const float*)d_in[20];
    const float* hw4 = (const float*)d_in[21];
    const float* hb4 = (const float*)d_in[22];
    float* out = (float*)d_out;

    float *h, *t1, *t2, *t3, *PQ;
    cudaGetSymbolAddress((void**)&h,  g_h);
    cudaGetSymbolAddress((void**)&t1, g_t1);
    cudaGetSymbolAddress((void**)&t2, g_t2);
    cudaGetSymbolAddress((void**)&t3, g_t3);
    cudaGetSymbolAddress((void**)&PQ, g_PQ);

    dim3 knn_grid(PTS/8, BATCH);
    int dg = NPTS*32/256;

    x0xsq_kernel<<<NPTS/256, 256>>>(feats, pos);                    // 1
    knn6_kernel<<<knn_grid, 256>>>();                               // 2
    pq6_kernel<<<NPTS*16/256, 256>>>(w1a, b1a);                     // 3
    edge_kernel<<<NEDGE/GBM, 128>>>(w1b);                           // 4 (profiled)
    decode_xsq_kernel<<<dg, 256>>>(b1b, 0);                         // 5

    // ---- layer 2 ----
    knn64_kernel<<<knn_grid, 128>>>(h, 192, 0);                     // 6
    run_gemm_pq(h, 0,  w2a, b2a, PQ);                               // 7
    edge_kernel<<<NEDGE/GBM, 128>>>(w2b);                           // 8
    decode_xsq_kernel<<<dg, 256>>>(b2b, 64);                        // 9

    // ---- layer 3 ----
    knn64_kernel<<<knn_grid, 128>>>(h, 192, 64);                    // 10
    run_gemm_pq(h, 64, w3a, b3a, PQ);                               // 11
    edge_kernel<<<NEDGE/GBM, 128>>>(w3b);                           // 12
    decode_xsq_kernel<<<dg, 256>>>(b3b, 128);                       // 13

    // ---- head ----
    run_gemm(h,  192,  0, hw1, hb1, t1, NPTS, 1024, 192, 1);        // 14
    run_gemm(t1, 1024, 0, hw2, hb2, t2, NPTS, 256, 1024, 1);        // 15
    run_gemm(t2, 256,  0, hw3, hb3, t3, NPTS, 128, 256, 1);         // 16
    head4_kernel<<<NPTS*32/256, 256>>>(hw4, hb4, out);              // 17
}

// round 16
// speedup vs baseline: 1.2464x; 1.0644x over previous
#include <cuda_runtime.h>
#include <math.h>

#define BATCH 8
#define PTS   2048
#define NPTS  (BATCH*PTS)      // 16384
#define KNN   20
#define NEDGE (NPTS*KNN)       // 327680

typedef unsigned long long u64;

// ---------------- scratch ----------------
__device__ __align__(16) float g_x0[NPTS*6];
__device__ __align__(16) float g_h [NPTS*192];
__device__ __align__(16) float g_xsq[NPTS];
__device__ __align__(16) int   g_knn[NEDGE];
__device__ __align__(16) float g_PQ[NPTS*128];
__device__ __align__(16) unsigned g_enc[NPTS*64];   // zero-init; decode_xsq re-zeroes
__device__ __align__(16) float g_t1[NPTS*1024];
__device__ __align__(16) float g_t2[NPTS*256];
__device__ __align__(16) float g_t3[NPTS*128];

// ---------------- packed f32x2 helpers ----------------
__device__ __forceinline__ void ffma2(u64& acc, u64 a, u64 b) {
    asm("fma.rn.f32x2 %0, %1, %2, %0;" : "+l"(acc) : "l"(a), "l"(b));
}
__device__ __forceinline__ u64 pack2(float lo, float hi) {
    u64 r; asm("mov.b64 %0, {%1, %2};" : "=l"(r) : "f"(lo), "f"(hi)); return r;
}
__device__ __forceinline__ float2 unpack2(u64 v) {
    float2 f; asm("mov.b64 {%0, %1}, %2;" : "=f"(f.x), "=f"(f.y) : "l"(v)); return f;
}
__device__ __forceinline__ unsigned encf(float f) {
    unsigned u = __float_as_uint(f);
    return (u & 0x80000000u) ? ~u : (u | 0x80000000u);
}
__device__ __forceinline__ float decf(unsigned e) {
    return __uint_as_float((e & 0x80000000u) ? (e & 0x7FFFFFFFu) : ~e);
}

// warp-distributed sorted top-K insert; thr = register copy of lane-19 key.
__device__ __forceinline__ void warp_accept(u64& slot, u64& thr, u64 key, int lane) {
    unsigned am = __ballot_sync(0xffffffffu, key < thr);
    while (am) {
        int l = __ffs(am) - 1; am &= am - 1;
        u64 nk = __shfl_sync(0xffffffffu, key, l);
        bool ins = nk < thr;
        unsigned m = __ballot_sync(0xffffffffu, slot > nk);
        u64 up = __shfl_up_sync(0xffffffffu, slot, 1);
        if (ins) {
            int pos = __ffs(m) - 1;
            if (lane == pos) slot = nk;
            else if (lane > pos) slot = up;
            thr = __shfl_sync(0xffffffffu, slot, 19);
        }
    }
}

// ---------------- build x0 + squared norm (fused) ----------------
__global__ void x0xsq_kernel(const float* __restrict__ feats, const float* __restrict__ pos) {
    int p = blockIdx.x * 256 + threadIdx.x;
    if (p >= NPTS) return;
    float v[6];
    v[0] = feats[p*3+0]; v[1] = feats[p*3+1]; v[2] = feats[p*3+2];
    v[3] = pos[p*3+0];   v[4] = pos[p*3+1];   v[5] = pos[p*3+2];
    float s = 0.f;
    #pragma unroll
    for (int f = 0; f < 6; f++) { g_x0[p*6+f] = v[f]; s += v[f]*v[f]; }
    g_xsq[p] = s;
}

// ---------------- warp-kNN, D=6 (candidate tile = 256) ----------------
__global__ __launch_bounds__(256) void knn6_kernel() {
    const int T = 256;
    __shared__ float cf[T*7];
    __shared__ float cn[T];
    int tid  = threadIdx.x;
    int lane = tid & 31;
    int w    = tid >> 5;
    int b    = blockIdx.y;
    int p    = b*PTS + blockIdx.x*8 + w;

    float xi[6];
    #pragma unroll
    for (int f = 0; f < 6; f++) xi[f] = g_x0[p*6 + f];
    float xin = g_xsq[p];

    u64 slot = ~0ULL, thr = ~0ULL;

    for (int t0 = 0; t0 < PTS; t0 += T) {
        int q0 = b*PTS + t0;
        __syncthreads();
        #pragma unroll
        for (int u = tid; u < T*6; u += 256) {
            int c = u / 6, f = u % 6;
            cf[c*7 + f] = g_x0[(q0 + c)*6 + f];
        }
        cn[tid] = g_xsq[q0 + tid];
        __syncthreads();
        #pragma unroll
        for (int r = 0; r < T/32; r++) {
            int c = r*32 + lane;
            float dot = 0.f;
            #pragma unroll
            for (int f = 0; f < 6; f++) dot += xi[f]*cf[c*7 + f];
            float dist = xin + cn[c] - 2.f*dot;
            u64 key = ((u64)encf(dist) << 32) | (unsigned)(q0 + c);
            warp_accept(slot, thr, key, lane);
        }
    }
    if (lane < KNN) g_knn[(size_t)p*KNN + lane] = (int)(slot & 0xFFFFFFFFu);
}

// ---------------- warp-kNN, D=64: warp handles 2 points, shared queries,
//                  q-chunk outer loop (amortized query LDS) ----------------
__global__ __launch_bounds__(128, 4) void knn64_kernel(const float* __restrict__ X,
                                                       int stride, int off) {
    const int T = 128;
    __shared__ float cf[T*68];
    __shared__ float cn[T];
    __shared__ float qs[8*64];       // 8 query rows for this block
    int tid  = threadIdx.x;
    int lane = tid & 31;
    int w    = tid >> 5;
    int b    = blockIdx.y;
    int pb   = b*PTS + blockIdx.x*8;
    int p0   = pb + w*2;
    int p1   = p0 + 1;

    // stage the block's 8 query rows into shared (coalesced, once)
    {
        int r  = tid >> 4;            // 0..7
        int c4 = (tid & 15) * 4;      // 0..60
        *(float4*)&qs[r*64 + c4] = *(const float4*)&X[(size_t)(pb + r)*stride + off + c4];
    }
    float xina = g_xsq[p0], xinb = g_xsq[p1];

    u64 sl0 = ~0ULL, th0 = ~0ULL, sl1 = ~0ULL, th1 = ~0ULL;
    const ulonglong2* qa = (const ulonglong2*)&qs[(w*2)*64];
    const ulonglong2* qb = (const ulonglong2*)&qs[(w*2+1)*64];

    for (int t0 = 0; t0 < PTS; t0 += T) {
        int q0 = b*PTS + t0;
        __syncthreads();
        #pragma unroll
        for (int u = tid; u < T*16; u += 128) {
            int c = u >> 4, fv = u & 15;
            *(float4*)&cf[c*68 + fv*4] =
                *(const float4*)&X[(size_t)(q0 + c)*stride + off + fv*4];
        }
        if (tid < T) cn[tid] = g_xsq[q0 + tid];
        __syncthreads();

        // partial-dot accumulators: 4 per point per round
        u64 accA[4][4], accB[4][4];
        #pragma unroll
        for (int r = 0; r < 4; r++)
            #pragma unroll
            for (int i = 0; i < 4; i++) { accA[r][i] = 0ULL; accB[r][i] = 0ULL; }

        #pragma unroll
        for (int q = 0; q < 16; q += 2) {
            ulonglong2 qa0 = qa[q], qa1 = qa[q+1];
            ulonglong2 qb0 = qb[q], qb1 = qb[q+1];
            #pragma unroll
            for (int r = 0; r < 4; r++) {
                const ulonglong2* cp = (const ulonglong2*)&cf[(r*32 + lane)*68];
                ulonglong2 v0 = cp[q];
                ulonglong2 v1 = cp[q+1];
                ffma2(accA[r][0], qa0.x, v0.x);  ffma2(accB[r][0], qb0.x, v0.x);
                ffma2(accA[r][1], qa0.y, v0.y);  ffma2(accB[r][1], qb0.y, v0.y);
                ffma2(accA[r][2], qa1.x, v1.x);  ffma2(accB[r][2], qb1.x, v1.x);
                ffma2(accA[r][3], qa1.y, v1.y);  ffma2(accB[r][3], qb1.y, v1.y);
            }
        }

        #pragma unroll
        for (int r = 0; r < 4; r++) {
            int c = r*32 + lane;
            float2 s0 = unpack2(accA[r][0]), s1 = unpack2(accA[r][1]);
            float2 s2 = unpack2(accA[r][2]), s3 = unpack2(accA[r][3]);
            float dota = ((s0.x+s0.y) + (s1.x+s1.y)) + ((s2.x+s2.y) + (s3.x+s3.y));
            s0 = unpack2(accB[r][0]); s1 = unpack2(accB[r][1]);
            s2 = unpack2(accB[r][2]); s3 = unpack2(accB[r][3]);
            float dotb = ((s0.x+s0.y) + (s1.x+s1.y)) + ((s2.x+s2.y) + (s3.x+s3.y));
            float da = xina + cn[c] - 2.f*dota;
            float db = xinb + cn[c] - 2.f*dotb;
            u64 ka = ((u64)encf(da) << 32) | (unsigned)(q0 + c);
            u64 kb = ((u64)encf(db) << 32) | (unsigned)(q0 + c);
            warp_accept(sl0, th0, ka, lane);
            warp_accept(sl1, th1, kb, lane);
        }
    }
    if (lane < KNN) {
        g_knn[(size_t)p0*KNN + lane] = (int)(sl0 & 0xFFFFFFFFu);
        g_knn[(size_t)p1*KNN + lane] = (int)(sl1 & 0xFFFFFFFFu);
    }
}

// ---------------- layer-1 P/Q (D=6) ----------------
__global__ void pq6_kernel(const float* __restrict__ w1a, const float* __restrict__ b1a) {
    int t = blockIdx.x * 256 + threadIdx.x;
    if (t >= NPTS*16) return;
    int p = t >> 4, c4 = (t & 15) * 4;
    float x[6];
    #pragma unroll
    for (int f = 0; f < 6; f++) x[f] = g_x0[p*6 + f];
    float4 P = *(const float4*)&b1a[c4];
    float4 Q = make_float4(0.f, 0.f, 0.f, 0.f);
    #pragma unroll
    for (int f = 0; f < 6; f++) {
        float4 wt = *(const float4*)&w1a[f*64 + c4];
        float4 wb = *(const float4*)&w1a[(6+f)*64 + c4];
        float4 wd = make_float4(wt.x - wb.x, wt.y - wb.y, wt.z - wb.z, wt.w - wb.w);
        P.x += x[f]*wd.x; P.y += x[f]*wd.y; P.z += x[f]*wd.z; P.w += x[f]*wd.w;
        Q.x += x[f]*wb.x; Q.y += x[f]*wb.y; Q.z += x[f]*wb.z; Q.w += x[f]*wb.w;
    }
    *(float4*)&g_PQ[p*128 + c4]      = P;
    *(float4*)&g_PQ[p*128 + 64 + c4] = Q;
}

// ---------------- fused decode + re-zero + xsq ----------------
__global__ void decode_xsq_kernel(const float* __restrict__ bias, int off) {
    int gt   = blockIdx.x * 256 + threadIdx.x;
    int p    = gt >> 5;
    int lane = threadIdx.x & 31;
    if (p >= NPTS) return;
    unsigned e0 = g_enc[p*64 + lane];
    unsigned e1 = g_enc[p*64 + 32 + lane];
    g_enc[p*64 + lane]      = 0u;
    g_enc[p*64 + 32 + lane] = 0u;
    float v0 = decf(e0) + bias[lane];
    float v1 = decf(e1) + bias[lane + 32];
    g_h[(size_t)p*192 + off + lane]      = v0;
    g_h[(size_t)p*192 + off + 32 + lane] = v1;
    float s = v0*v0 + v1*v1;
    #pragma unroll
    for (int d = 16; d; d >>= 1) s += __shfl_xor_sync(0xffffffffu, s, d);
    if (lane == 0) g_xsq[p] = s;
}

// ---------------- plain / PQ GEMM: 256x64 block, 128 threads, 16x8 microtile ----------------
#define GBM2 256
#define GBN 64
#define GBK 16

template<int MODE>
__device__ __forceinline__ void load_wtile(const float* __restrict__ W, int N,
                                           int n0, int wn, int kr,
                                           float4& w0v, float4& w1v) {
    if (MODE == 0) {
        const float* Wr = W + (size_t)kr*N + n0 + wn;
        w0v = *(const float4*)Wr;
        w1v = *(const float4*)(Wr + 4);
    } else {
        if (n0 == 0) {
            const float* Wt = W + (size_t)kr*64 + wn;
            const float* Wb = W + (size_t)(64 + kr)*64 + wn;
            float4 t0 = *(const float4*)Wt, t1 = *(const float4*)(Wt + 4);
            float4 b0 = *(const float4*)Wb, b1 = *(const float4*)(Wb + 4);
            w0v = make_float4(t0.x-b0.x, t0.y-b0.y, t0.z-b0.z, t0.w-b0.w);
            w1v = make_float4(t1.x-b1.x, t1.y-b1.y, t1.z-b1.z, t1.w-b1.w);
        } else {
            const float* Wb = W + (size_t)(64 + kr)*64 + wn;
            w0v = *(const float4*)Wb;
            w1v = *(const float4*)(Wb + 4);
        }
    }
}

template<int MODE>
__global__ __launch_bounds__(128) void gemm_kernel(
        const float* __restrict__ A, int lda, int aoff,
        const float* __restrict__ W, const float* __restrict__ bias,
        float* __restrict__ C, int M, int N, int Kd, int do_relu) {
    __shared__ float As[GBK][GBM2+4];
    __shared__ float Ws[GBK][GBN];

    int t  = threadIdx.x;
    int m0 = blockIdx.x * GBM2;
    int n0 = blockIdx.y * GBN;
    int ty = t >> 3, tx = t & 7;
    int arow = t >> 2;
    int acol = (t & 3) * 4;
    int wk = t >> 3, wn = (t & 7) * 8;

    u64 acc[8][8];
    #pragma unroll
    for (int i = 0; i < 8; i++)
        #pragma unroll
        for (int j = 0; j < 8; j++) acc[i][j] = 0ULL;

    const float* A0 = A + aoff + (size_t)(m0 + arow)*lda + acol;

    float4 aR[8], w0v, w1v;
    #pragma unroll
    for (int i = 0; i < 8; i++)
        aR[i] = *(const float4*)(A0 + (size_t)(32*i)*lda);
    load_wtile<MODE>(W, N, n0, wn, wk, w0v, w1v);

    for (int kk = 0; kk < Kd; kk += GBK) {
        __syncthreads();
        #pragma unroll
        for (int i = 0; i < 8; i++) {
            As[acol+0][arow + 32*i] = aR[i].x;
            As[acol+1][arow + 32*i] = aR[i].y;
            As[acol+2][arow + 32*i] = aR[i].z;
            As[acol+3][arow + 32*i] = aR[i].w;
        }
        *(float4*)&Ws[wk][wn]     = w0v;
        *(float4*)&Ws[wk][wn + 4] = w1v;
        __syncthreads();
        if (kk + GBK < Kd) {
            #pragma unroll
            for (int i = 0; i < 8; i++)
                aR[i] = *(const float4*)(A0 + (kk + GBK) + (size_t)(32*i)*lda);
            load_wtile<MODE>(W, N, n0, wn, kk + GBK + wk, w0v, w1v);
        }
        #pragma unroll
        for (int k = 0; k < GBK; k++) {
            ulonglong2 aA = *(const ulonglong2*)&As[k][ty*16];
            ulonglong2 aB = *(const ulonglong2*)&As[k][ty*16 + 4];
            ulonglong2 aC = *(const ulonglong2*)&As[k][ty*16 + 8];
            ulonglong2 aD = *(const ulonglong2*)&As[k][ty*16 + 12];
            u64 am[8] = {aA.x, aA.y, aB.x, aB.y, aC.x, aC.y, aD.x, aD.y};
            float4 w0 = *(const float4*)&Ws[k][tx*8];
            float4 w1 = *(const float4*)&Ws[k][tx*8 + 4];
            u64 wp[8];
            wp[0] = pack2(w0.x, w0.x); wp[1] = pack2(w0.y, w0.y);
            wp[2] = pack2(w0.z, w0.z); wp[3] = pack2(w0.w, w0.w);
            wp[4] = pack2(w1.x, w1.x); wp[5] = pack2(w1.y, w1.y);
            wp[6] = pack2(w1.z, w1.z); wp[7] = pack2(w1.w, w1.w);
            #pragma unroll
            for (int i = 0; i < 8; i++)
                #pragma unroll
                for (int j = 0; j < 8; j++)
                    ffma2(acc[i][j], am[i], wp[j]);
        }
    }

    float bb[8];
    if (MODE == 1 && n0 != 0) {
        #pragma unroll
        for (int j = 0; j < 8; j++) bb[j] = 0.f;
    } else {
        float4 bz0 = *(const float4*)&bias[n0 + tx*8];
        float4 bz1 = *(const float4*)&bias[n0 + tx*8 + 4];
        bb[0]=bz0.x; bb[1]=bz0.y; bb[2]=bz0.z; bb[3]=bz0.w;
        bb[4]=bz1.x; bb[5]=bz1.y; bb[6]=bz1.z; bb[7]=bz1.w;
    }
    #pragma unroll
    for (int i = 0; i < 8; i++) {
        float lo[8], hi[8];
        #pragma unroll
        for (int j = 0; j < 8; j++) {
            float2 v = unpack2(acc[i][j]);
            lo[j] = v.x + bb[j]; hi[j] = v.y + bb[j];
            if (do_relu) { lo[j] = fmaxf(lo[j], 0.f); hi[j] = fmaxf(hi[j], 0.f); }
        }
        int m = m0 + ty*16 + 2*i;
        float* Cr0 = &C[(size_t)m*N + n0 + tx*8];
        float* Cr1 = Cr0 + N;
        *(float4*)Cr0       = make_float4(lo[0],lo[1],lo[2],lo[3]);
        *(float4*)(Cr0 + 4) = make_float4(lo[4],lo[5],lo[6],lo[7]);
        *(float4*)Cr1       = make_float4(hi[0],hi[1],hi[2],hi[3]);
        *(float4*)(Cr1 + 4) = make_float4(hi[4],hi[5],hi[6],hi[7]);
    }
}

// ---------------- fused edge kernel: double-buffered, 1 sync per k-tile ----------------
#define GBM 128

struct AccBlk { u64 a[4][8]; };

__device__ __forceinline__ void mt_compute(AccBlk& A_, const float As[GBK][GBM+4],
                                           const float Ws[GBK][GBN], int ty, int tx) {
    #pragma unroll
    for (int k = 0; k < GBK; k++) {
        ulonglong2 aA = *(const ulonglong2*)&As[k][ty*8];
        ulonglong2 aB = *(const ulonglong2*)&As[k][ty*8 + 4];
        u64 am[4] = {aA.x, aA.y, aB.x, aB.y};
        float4 w0 = *(const float4*)&Ws[k][tx*8];
        float4 w1 = *(const float4*)&Ws[k][tx*8 + 4];
        u64 wp[8];
        wp[0] = pack2(w0.x, w0.x); wp[1] = pack2(w0.y, w0.y);
        wp[2] = pack2(w0.z, w0.z); wp[3] = pack2(w0.w, w0.w);
        wp[4] = pack2(w1.x, w1.x); wp[5] = pack2(w1.y, w1.y);
        wp[6] = pack2(w1.z, w1.z); wp[7] = pack2(w1.w, w1.w);
        #pragma unroll
        for (int i = 0; i < 4; i++)
            #pragma unroll
            for (int j = 0; j < 8; j++)
                ffma2(A_.a[i][j], am[i], wp[j]);
    }
}

__global__ __launch_bounds__(128, 4) void edge_kernel(const float* __restrict__ W2) {
    __shared__ float As[2][GBK][GBM+4];
    __shared__ float Ws[2][GBK][GBN];
    __shared__ int   jb[GBM];

    int t  = threadIdx.x;
    int m0 = blockIdx.x * GBM;
    int ty = t >> 3, tx = t & 7;

    AccBlk acc;
    #pragma unroll
    for (int i = 0; i < 4; i++)
        #pragma unroll
        for (int j = 0; j < 8; j++) acc.a[i][j] = 0ULL;

    jb[t] = g_knn[m0 + t];
    int srow = t >> 2;
    int sc4  = (t & 3) * 4;
    int wk = t >> 3, wn = (t & 7) * 8;
    __syncthreads();

    float4 p4[4], q4[4], w0v, w1v;
    #pragma unroll
    for (int i = 0; i < 4; i++) {
        int row = srow + 32*i;
        int pb  = (m0 + row) / KNN;
        p4[i] = *(const float4*)&g_PQ[(size_t)pb*128 + sc4];
        q4[i] = *(const float4*)&g_PQ[(size_t)jb[row]*128 + 64 + sc4];
    }
    {
        const float* Wr = &W2[(size_t)wk*64 + wn];
        w0v = *(const float4*)Wr;
        w1v = *(const float4*)(Wr + 4);
    }

    #pragma unroll
    for (int kt = 0; kt < 4; kt++) {
        int buf = kt & 1;
        #pragma unroll
        for (int i = 0; i < 4; i++) {
            int row = srow + 32*i;
            As[buf][sc4+0][row] = fmaxf(p4[i].x + q4[i].x, 0.f);
            As[buf][sc4+1][row] = fmaxf(p4[i].y + q4[i].y, 0.f);
            As[buf][sc4+2][row] = fmaxf(p4[i].z + q4[i].z, 0.f);
            As[buf][sc4+3][row] = fmaxf(p4[i].w + q4[i].w, 0.f);
        }
        *(float4*)&Ws[buf][wk][wn]     = w0v;
        *(float4*)&Ws[buf][wk][wn + 4] = w1v;
        __syncthreads();
        if (kt < 3) {
            int kn = (kt + 1) * GBK;
            #pragma unroll
            for (int i = 0; i < 4; i++) {
                int row = srow + 32*i;
                int pb  = (m0 + row) / KNN;
                p4[i] = *(const float4*)&g_PQ[(size_t)pb*128 + kn + sc4];
                q4[i] = *(const float4*)&g_PQ[(size_t)jb[row]*128 + 64 + kn + sc4];
            }
            const float* Wr = &W2[(size_t)(kn + wk)*64 + wn];
            w0v = *(const float4*)Wr;
            w1v = *(const float4*)(Wr + 4);
        }
        mt_compute(acc, As[buf], Ws[buf], ty, tx);
    }

    int mb = m0 + ty*8;
    int curp = mb / KNN;
    float mx[8];
    #pragma unroll
    for (int j = 0; j < 8; j++) mx[j] = -3.4e38f;
    #pragma unroll
    for (int i = 0; i < 4; i++) {
        #pragma unroll
        for (int half = 0; half < 2; half++) {
            int rr = mb + 2*i + half;
            int pp = rr / KNN;
            if (pp != curp) {
                #pragma unroll
                for (int j = 0; j < 8; j++)
                    atomicMax(&g_enc[curp*64 + tx*8 + j], encf(mx[j]));
                curp = pp;
                #pragma unroll
                for (int j = 0; j < 8; j++) mx[j] = -3.4e38f;
            }
            #pragma unroll
            for (int j = 0; j < 8; j++) {
                float2 v = unpack2(acc.a[i][j]);
                float val = half ? v.y : v.x;
                mx[j] = fmaxf(mx[j], val);
            }
        }
    }
    #pragma unroll
    for (int j = 0; j < 8; j++)
        atomicMax(&g_enc[curp*64 + tx*8 + j], encf(mx[j]));
}

// ---------------- head final: 128->13 + log_softmax ----------------
__global__ void head4_kernel(const float* __restrict__ W,
                             const float* __restrict__ bias,
                             float* __restrict__ out) {
    int gt   = blockIdx.x * 256 + threadIdx.x;
    int warp = gt >> 5;
    int lane = threadIdx.x & 31;
    if (warp >= NPTS) return;
    float o = -3.4e38f;
    if (lane < 13) {
        float s = bias[lane];
        #pragma unroll 8
        for (int c = 0; c < 128; c++)
            s += g_t3[(size_t)warp*128 + c] * W[c*13 + lane];
        o = s;
    }
    float m = o;
    #pragma unroll
    for (int d = 16; d; d >>= 1) m = fmaxf(m, __shfl_xor_sync(0xffffffffu, m, d));
    float e = (lane < 13) ? expf(o - m) : 0.f;
    float ssum = e;
    #pragma unroll
    for (int d = 16; d; d >>= 1) ssum += __shfl_xor_sync(0xffffffffu, ssum, d);
    if (lane < 13) out[(size_t)warp*13 + lane] = o - m - logf(ssum);
}

// ---------------- host ----------------
static inline void run_gemm(const float* A, int lda, int aoff, const float* W,
                            const float* b, float* C, int M, int N, int Kd, int relu) {
    dim3 grid(M/GBM2, N/GBN);
    gemm_kernel<0><<<grid, 128>>>(A, lda, aoff, W, b, C, M, N, Kd, relu);
}
static inline void run_gemm_pq(const float* A, int aoff, const float* W,
                               const float* b, float* C) {
    dim3 grid(NPTS/GBM2, 2);
    gemm_kernel<1><<<grid, 128>>>(A, 192, aoff, W, b, C, NPTS, 128, 64, 0);
}

extern "C" void kernel_launch(void* const* d_in, const int* in_sizes, int n_in,
                              void* d_out, int out_size) {
    const float* feats = (const float*)d_in[0];
    const float* pos   = (const float*)d_in[1];
    const float* w1a = (const float*)d_in[3];
    const float* b1a = (const float*)d_in[4];
    const float* w1b = (const float*)d_in[5];
    const float* b1b = (const float*)d_in[6];
    const float* w2a = (const float*)d_in[7];
    const float* b2a = (const float*)d_in[8];
    const float* w2b = (const float*)d_in[9];
    const float* b2b = (const float*)d_in[10];
    const float* w3a = (const float*)d_in[11];
    const float* b3a = (const float*)d_in[12];
    const float* w3b = (const float*)d_in[13];
    const float* b3b = (const float*)d_in[14];
    const float* hw1 = (const float*)d_in[15];
    const float* hb1 = (const float*)d_in[16];
    const float* hw2 = (const float*)d_in[17];
    const float* hb2 = (const float*)d_in[18];
    const float* hw3 = (const float*)d_in[19];
    const float* hb3 = (const float*)d_in[20];
    const float* hw4 = (const float*)d_in[21];
    const float* hb4 = (const float*)d_in[22];
    float* out = (float*)d_out;

    float *h, *t1, *t2, *t3, *PQ;
    cudaGetSymbolAddress((void**)&h,  g_h);
    cudaGetSymbolAddress((void**)&t1, g_t1);
    cudaGetSymbolAddress((void**)&t2, g_t2);
    cudaGetSymbolAddress((void**)&t3, g_t3);
    cudaGetSymbolAddress((void**)&PQ, g_PQ);

    dim3 knn_grid(PTS/8, BATCH);
    int dg = NPTS*32/256;

    x0xsq_kernel<<<NPTS/256, 256>>>(feats, pos);                    // 1
    knn6_kernel<<<knn_grid, 256>>>();                               // 2
    pq6_kernel<<<NPTS*16/256, 256>>>(w1a, b1a);                     // 3
    edge_kernel<<<NEDGE/GBM, 128>>>(w1b);                           // 4 (profiled)
    decode_xsq_kernel<<<dg, 256>>>(b1b, 0);                         // 5

    // ---- layer 2 ----
    knn64_kernel<<<knn_grid, 128>>>(h, 192, 0);                     // 6
    run_gemm_pq(h, 0,  w2a, b2a, PQ);                               // 7
    edge_kernel<<<NEDGE/GBM, 128>>>(w2b);                           // 8
    decode_xsq_kernel<<<dg, 256>>>(b2b, 64);                        // 9

    // ---- layer 3 ----
    knn64_kernel<<<knn_grid, 128>>>(h, 192, 64);                    // 10
    run_gemm_pq(h, 64, w3a, b3a, PQ);                               // 11
    edge_kernel<<<NEDGE/GBM, 128>>>(w3b);                           // 12
    decode_xsq_kernel<<<dg, 256>>>(b3b, 128);                       // 13

    // ---- head ----
    run_gemm(h,  192,  0, hw1, hb1, t1, NPTS, 1024, 192, 1);        // 14
    run_gemm(t1, 1024, 0, hw2, hb2, t2, NPTS, 256, 1024, 1);        // 15
    run_gemm(t2, 256,  0, hw3, hb3, t3, NPTS, 128, 256, 1);         // 16
    head4_kernel<<<NPTS*32/256, 256>>>(hw4, hb4, out);              // 17
}